// round 8
// baseline (speedup 1.0000x reference)
#include <cuda_runtime.h>
#include <cuda_bf16.h>
#include <cstdint>
#include <math.h>

#define BB 8
#define DD 512
#define LL 2048
#define HH 8
#define OT 1536

// bf16 hi/lo scratch, pre-swizzled (SW128 chunk permutation by row&7 applied in gmem)
// q,k: [b][l][512] (per-head 64 cols = 128B rows);  v: [b][dh 512][l]
__device__ __nv_bfloat16 g_qhi[(size_t)BB * LL * DD], g_qlo[(size_t)BB * LL * DD];
__device__ __nv_bfloat16 g_khi[(size_t)BB * LL * DD], g_klo[(size_t)BB * LL * DD];
__device__ __nv_bfloat16 g_vhi[(size_t)BB * DD * LL], g_vlo[(size_t)BB * DD * LL];

// ============================ helpers ======================================
__device__ __forceinline__ uint32_t smem_u32(const void* p) {
    uint32_t a;
    asm("{ .reg .u64 t; cvta.to.shared.u64 t, %1; cvt.u32.u64 %0, t; }"
        : "=r"(a) : "l"(p));
    return a;
}

#define SWZ128(off) ((off) ^ (((off) >> 3) & 0x70))

__device__ __forceinline__ void ldsm4(uint32_t* r, uint32_t addr) {
    asm volatile("ldmatrix.sync.aligned.m8n8.x4.shared.b16 {%0,%1,%2,%3}, [%4];"
        : "=r"(r[0]), "=r"(r[1]), "=r"(r[2]), "=r"(r[3]) : "r"(addr));
}

__device__ __forceinline__ void ldsm4t(uint32_t* r, uint32_t addr) {
    asm volatile("ldmatrix.sync.aligned.m8n8.x4.trans.shared.b16 {%0,%1,%2,%3}, [%4];"
        : "=r"(r[0]), "=r"(r[1]), "=r"(r[2]), "=r"(r[3]) : "r"(addr));
}

__device__ __forceinline__ void mma16816(float* d, const uint32_t* a, const uint32_t* b) {
    asm volatile("mma.sync.aligned.m16n8k16.row.col.f32.bf16.bf16.f32 "
        "{%0,%1,%2,%3}, {%4,%5,%6,%7}, {%8,%9}, {%0,%1,%2,%3};"
        : "+f"(d[0]), "+f"(d[1]), "+f"(d[2]), "+f"(d[3])
        : "r"(a[0]), "r"(a[1]), "r"(a[2]), "r"(a[3]), "r"(b[0]), "r"(b[1]));
}

__device__ __forceinline__ void cpa16(uint32_t sdst, const void* gsrc) {
    asm volatile("cp.async.cg.shared.global [%0], [%1], 16;"
        :: "r"(sdst), "l"(gsrc));
}
#define CPA_COMMIT() asm volatile("cp.async.commit_group;" ::: "memory")
#define CPA_WAIT(n)  asm volatile("cp.async.wait_group %0;" :: "n"(n) : "memory")

// split fp32x4 -> bf16 hi/lo pairs, store swizzled into smem (proj staging)
__device__ __forceinline__ void cvt_store4(char* smem, uint32_t hi_off, uint32_t lo_off,
                                           uint32_t byte_off, float4 v) {
    __nv_bfloat162 h0, h1, l0, l1;
    h0.x = __float2bfloat16_rn(v.x); h0.y = __float2bfloat16_rn(v.y);
    h1.x = __float2bfloat16_rn(v.z); h1.y = __float2bfloat16_rn(v.w);
    l0.x = __float2bfloat16_rn(v.x - __bfloat162float(h0.x));
    l0.y = __float2bfloat16_rn(v.y - __bfloat162float(h0.y));
    l1.x = __float2bfloat16_rn(v.z - __bfloat162float(h1.x));
    l1.y = __float2bfloat16_rn(v.w - __bfloat162float(h1.y));
    uint32_t s = SWZ128(byte_off);
    *(__nv_bfloat162*)(smem + hi_off + s)     = h0;
    *(__nv_bfloat162*)(smem + hi_off + s + 4) = h1;
    *(__nv_bfloat162*)(smem + lo_off + s)     = l0;
    *(__nv_bfloat162*)(smem + lo_off + s + 4) = l1;
}

// ===========================================================================
// Projection GEMM (tensor pipe): out2[o][l] = sum_d W[o][d]*q[d][l], then
// epilogue converts to bf16 hi/lo and stores PRE-SWIZZLED to gmem.
// ===========================================================================
#define PA_HI  0
#define PA_LO  16384
#define PB0_HI 32768
#define PB0_LO 40960
#define PB1_HI 49152
#define PB1_LO 57344
#define OSTRIDE 132
#define P_TOTAL (128 * OSTRIDE * 4)   // 67584

__global__ __launch_bounds__(256, 2) void proj_mma(
    const float* __restrict__ qin,
    const float* __restrict__ w_mem,
    const float* __restrict__ w_q)
{
    extern __shared__ char smem[];
    const uint32_t sb = smem_u32(smem);
    const int tid = threadIdx.x;
    const int w = tid >> 5, lane = tid & 31;
    const int b  = blockIdx.z;
    const int l0 = blockIdx.x * 128;
    const int o0 = blockIdx.y * 128;

    const float* wptr = (o0 < 1024) ? (w_mem + (size_t)o0 * DD)
                                    : (w_q  + (size_t)(o0 - 1024) * DD);
    const float* qb = qin + (size_t)b * DD * LL;

    const int mi     = lane >> 3;
    const int arow   = w * 16 + ((mi & 1) << 3) + (lane & 7);
    const int acolh  = (mi >> 1) * 16;
    const int b_ksub = ((mi & 1) << 3) + (lane & 7);
    const int b_noct = mi >> 1;

    float c[16][4];
    #pragma unroll
    for (int i = 0; i < 16; i++)
        #pragma unroll
        for (int j = 0; j < 4; j++) c[i][j] = 0.f;

    for (int kc = 0; kc < 8; kc++) {
        __syncthreads();
        #pragma unroll
        for (int i = tid; i < 128 * 16; i += 256) {
            int row = i >> 4, d4 = (i & 15) << 2;
            float4 v = *(const float4*)(wptr + (size_t)row * DD + kc * 64 + d4);
            cvt_store4(smem, PA_HI, PA_LO, (uint32_t)(row * 128 + d4 * 2), v);
        }
        #pragma unroll
        for (int i = tid; i < 64 * 32; i += 256) {
            int row = i >> 5, l4 = (i & 31) << 2;
            float4 v = *(const float4*)(qb + (size_t)(kc * 64 + row) * LL + l0 + l4);
            uint32_t hi = (l4 & 64) ? PB1_HI : PB0_HI;
            uint32_t lo = (l4 & 64) ? PB1_LO : PB0_LO;
            cvt_store4(smem, hi, lo, (uint32_t)(row * 128 + (l4 & 63) * 2), v);
        }
        __syncthreads();

        #pragma unroll
        for (int ks = 0; ks < 4; ks++) {
            uint32_t ahi[4], alo[4];
            uint32_t aoff = (uint32_t)(arow * 128 + ks * 32 + acolh);
            ldsm4(ahi, sb + PA_HI + SWZ128(aoff));
            ldsm4(alo, sb + PA_LO + SWZ128(aoff));
            #pragma unroll
            for (int hb = 0; hb < 2; hb++) {
                const uint32_t bh = sb + (hb ? PB1_HI : PB0_HI);
                const uint32_t bl = sb + (hb ? PB1_LO : PB0_LO);
                #pragma unroll
                for (int j = 0; j < 8; j += 2) {
                    uint32_t boff = (uint32_t)((ks * 16 + b_ksub) * 128 + (j + b_noct) * 16);
                    uint32_t bhi[4], blo[4];
                    ldsm4t(bhi, bh + SWZ128(boff));
                    ldsm4t(blo, bl + SWZ128(boff));
                    const int o1 = hb * 8 + j;
                    mma16816(c[o1],     ahi, bhi);
                    mma16816(c[o1],     ahi, blo);
                    mma16816(c[o1],     alo, bhi);
                    mma16816(c[o1 + 1], ahi, bhi + 2);
                    mma16816(c[o1 + 1], ahi, blo + 2);
                    mma16816(c[o1 + 1], alo, bhi + 2);
                }
            }
        }
    }

    // ---- fragments -> smem [o][OSTRIDE] fp32 ----
    __syncthreads();
    float* Osm = (float*)smem;
    {
        const int r1 = w * 16 + (lane >> 2);
        const int cb = (lane & 3) << 1;
        #pragma unroll
        for (int oct = 0; oct < 16; oct++) {
            const int col = (oct >> 3) * 64 + (oct & 7) * 8 + cb;
            Osm[r1 * OSTRIDE + col]           = c[oct][0];
            Osm[r1 * OSTRIDE + col + 1]       = c[oct][1];
            Osm[(r1 + 8) * OSTRIDE + col]     = c[oct][2];
            Osm[(r1 + 8) * OSTRIDE + col + 1] = c[oct][3];
        }
    }
    __syncthreads();

    if (o0 >= 512 && o0 < 1024) {
        // V: rows are dh; store [dh][l] pre-swizzled (chunk perm by dh&7 per 128B seg)
        #pragma unroll
        for (int i = tid; i < 2048; i += 256) {
            int row = i >> 4, ch = i & 15;
            int vr = (o0 - 512) + row;
            const float* src = &Osm[row * OSTRIDE + ch * 8];
            __align__(16) __nv_bfloat16 hi8[8], lo8[8];
            #pragma unroll
            for (int k = 0; k < 8; k++) {
                float x = src[k];
                __nv_bfloat16 hx = __float2bfloat16_rn(x);
                hi8[k] = hx;
                lo8[k] = __float2bfloat16_rn(x - __bfloat162float(hx));
            }
            int seg = ch >> 3, pc = (ch & 7) ^ (vr & 7);
            size_t ge = ((size_t)b * DD + vr) * LL + l0 + seg * 64 + pc * 8;
            *(uint4*)&g_vhi[ge] = *(uint4*)hi8;
            *(uint4*)&g_vlo[ge] = *(uint4*)lo8;
        }
    } else {
        // K/Q: store transposed [l][512] pre-swizzled (chunk perm by l&7 per head seg)
        const float sc = (o0 >= 1024) ? 0.125f : 1.0f;
        __nv_bfloat16* ah = (o0 < 512) ? g_khi : g_qhi;
        __nv_bfloat16* al = (o0 < 512) ? g_klo : g_qlo;
        #pragma unroll
        for (int i = tid; i < 2048; i += 256) {
            int l = i >> 4, ch = i & 15;
            int gl = l0 + l;
            __align__(16) __nv_bfloat16 hi8[8], lo8[8];
            #pragma unroll
            for (int k = 0; k < 8; k++) {
                int rk = (k + lane) & 7;      // staggered to break smem bank conflicts
                float x = Osm[(ch * 8 + rk) * OSTRIDE + l] * sc;
                __nv_bfloat16 hx = __float2bfloat16_rn(x);
                hi8[rk] = hx;
                lo8[rk] = __float2bfloat16_rn(x - __bfloat162float(hx));
            }
            int seg = ch >> 3, pc = (ch & 7) ^ (gl & 7);
            size_t ge = ((size_t)b * LL + gl) * DD + (o0 & 511) + seg * 64 + pc * 8;
            *(uint4*)&ah[ge] = *(uint4*)hi8;
            *(uint4*)&al[ge] = *(uint4*)lo8;
        }
    }
}

// ===========================================================================
// mma.sync flash attention with cp.async double-buffered staging.
// Gmem tiles are pre-swizzled -> staging is pure 16B copies.
// ===========================================================================
#define SM_QHI   0
#define SM_QLO   16384
#define ST_BASE  32768
#define ST_SIZE  33024            // KHI 8K | KLO 8K | VHI 8K | VLO 8K | MSK 256
#define SM_TOTAL (ST_BASE + 2 * ST_SIZE)   // 98816

__global__ __launch_bounds__(256, 2) void attn_mma(
    const int* __restrict__ mask, float* __restrict__ out)
{
    extern __shared__ char smem[];
    const uint32_t sb = smem_u32(smem);
    const int tid  = threadIdx.x;
    const int w    = tid >> 5;
    const int lane = tid & 31;
    const int b = blockIdx.z, h = blockIdx.y, q0 = blockIdx.x * 128;

    const size_t qkrow0 = (size_t)b * LL * DD + (size_t)h * 64;   // + l*DD
    const size_t vrow0  = ((size_t)b * DD + h * 64) * LL;         // + dh*LL

    // ---- stage Q (group 0, with tile 0) ----
    #pragma unroll
    for (int j = 0; j < 4; j++) {
        int i = tid + j * 256;            // 0..1023
        int row = i >> 3, ch = i & 7;
        size_t ge = qkrow0 + (size_t)(q0 + row) * DD + ch * 8;
        cpa16(sb + SM_QHI + row * 128 + ch * 16, g_qhi + ge);
        cpa16(sb + SM_QLO + row * 128 + ch * 16, g_qlo + ge);
    }
    // ---- prefetch tile 0 ----
    {
        const uint32_t st = sb + ST_BASE;
        #pragma unroll
        for (int j = 0; j < 2; j++) {
            int i = tid + j * 256;        // 0..511
            int row = i >> 3, ch = i & 7;
            size_t ke = qkrow0 + (size_t)row * DD + ch * 8;
            cpa16(st + row * 128 + ch * 16,         g_khi + ke);
            cpa16(st + 8192 + row * 128 + ch * 16,  g_klo + ke);
            size_t ve = vrow0 + (size_t)row * LL + ch * 8;
            cpa16(st + 16384 + row * 128 + ch * 16, g_vhi + ve);
            cpa16(st + 24576 + row * 128 + ch * 16, g_vlo + ve);
        }
        if (tid < 16) cpa16(st + 32768 + tid * 16, mask + (size_t)b * LL + tid * 4);
    }
    CPA_COMMIT();

    const int mi = lane >> 3;
    const int qrow_l = w * 16 + ((mi & 1) << 3) + (lane & 7);
    const int a_colh = (mi >> 1) * 16;
    const int b_rsub = ((mi >> 1) << 3) + (lane & 7);
    const int b_colh = (mi & 1) * 16;

    float o_acc[8][4];
    #pragma unroll
    for (int i = 0; i < 8; i++)
        #pragma unroll
        for (int j = 0; j < 4; j++) o_acc[i][j] = 0.f;
    float lsum0 = 0.f, lsum1 = 0.f;

    for (int it = 0; it < 32; it++) {
        if (it + 1 < 32) {
            const int k1 = (it + 1) * 64;
            const uint32_t st = sb + ST_BASE + ((it + 1) & 1) * ST_SIZE;
            #pragma unroll
            for (int j = 0; j < 2; j++) {
                int i = tid + j * 256;
                int row = i >> 3, ch = i & 7;
                size_t ke = qkrow0 + (size_t)(k1 + row) * DD + ch * 8;
                cpa16(st + row * 128 + ch * 16,         g_khi + ke);
                cpa16(st + 8192 + row * 128 + ch * 16,  g_klo + ke);
                size_t ve = vrow0 + (size_t)row * LL + k1 + ch * 8;
                cpa16(st + 16384 + row * 128 + ch * 16, g_vhi + ve);
                cpa16(st + 24576 + row * 128 + ch * 16, g_vlo + ve);
            }
            if (tid < 16) cpa16(st + 32768 + tid * 16, mask + (size_t)b * LL + k1 + tid * 4);
            CPA_COMMIT();
            CPA_WAIT(1);
        } else {
            CPA_WAIT(0);
        }
        __syncthreads();

        const uint32_t st = sb + ST_BASE + (it & 1) * ST_SIZE;
        const uint32_t kh = st, kl = st + 8192, vh = st + 16384, vl = st + 24576;
        const int* mp = (const int*)(smem + (ST_BASE + (it & 1) * ST_SIZE + 32768));

        // ---- S = Q.K^T ----
        float s[8][4];
        #pragma unroll
        for (int i = 0; i < 8; i++)
            #pragma unroll
            for (int j = 0; j < 4; j++) s[i][j] = 0.f;

        #pragma unroll
        for (int kc = 0; kc < 4; kc++) {
            uint32_t ahi[4], alo[4];
            uint32_t qoff = (uint32_t)(qrow_l * 128 + kc * 32 + a_colh);
            ldsm4(ahi, sb + SM_QHI + SWZ128(qoff));
            ldsm4(alo, sb + SM_QLO + SWZ128(qoff));
            #pragma unroll
            for (int j = 0; j < 8; j += 2) {
                uint32_t bhi[4], blo[4];
                uint32_t koff = (uint32_t)((j * 8 + b_rsub) * 128 + kc * 32 + b_colh);
                ldsm4(bhi, kh + SWZ128(koff));
                ldsm4(blo, kl + SWZ128(koff));
                mma16816(s[j],     ahi, bhi);
                mma16816(s[j],     ahi, blo);
                mma16816(s[j],     alo, bhi);
                mma16816(s[j + 1], ahi, bhi + 2);
                mma16816(s[j + 1], ahi, blo + 2);
                mma16816(s[j + 1], alo, bhi + 2);
            }
        }

        // ---- softmax + P packing ----
        uint32_t phiA[8], phiB[8], ploA[8], ploB[8];
        #pragma unroll
        for (int nt = 0; nt < 8; nt++) {
            const int c0 = nt * 8 + ((lane & 3) << 1);
            const bool m0v = mp[c0] != 0, m1v = mp[c0 + 1] != 0;
            float p0 = m0v ? __expf(s[nt][0]) : 0.f;
            float p1 = m1v ? __expf(s[nt][1]) : 0.f;
            float p2 = m0v ? __expf(s[nt][2]) : 0.f;
            float p3 = m1v ? __expf(s[nt][3]) : 0.f;
            lsum0 += p0 + p1;
            lsum1 += p2 + p3;
            __nv_bfloat162 hA, hB, lA, lB;
            hA.x = __float2bfloat16_rn(p0); hA.y = __float2bfloat16_rn(p1);
            hB.x = __float2bfloat16_rn(p2); hB.y = __float2bfloat16_rn(p3);
            lA.x = __float2bfloat16_rn(p0 - __bfloat162float(hA.x));
            lA.y = __float2bfloat16_rn(p1 - __bfloat162float(hA.y));
            lB.x = __float2bfloat16_rn(p2 - __bfloat162float(hB.x));
            lB.y = __float2bfloat16_rn(p3 - __bfloat162float(hB.y));
            phiA[nt] = *(uint32_t*)&hA; phiB[nt] = *(uint32_t*)&hB;
            ploA[nt] = *(uint32_t*)&lA; ploB[nt] = *(uint32_t*)&lB;
        }

        // ---- O += P.V ----
        #pragma unroll
        for (int kc = 0; kc < 4; kc++) {
            uint32_t ahi[4] = {phiA[2 * kc], phiB[2 * kc], phiA[2 * kc + 1], phiB[2 * kc + 1]};
            uint32_t alo[4] = {ploA[2 * kc], ploB[2 * kc], ploA[2 * kc + 1], ploB[2 * kc + 1]};
            #pragma unroll
            for (int j = 0; j < 8; j += 2) {
                uint32_t bhi[4], blo[4];
                uint32_t voff = (uint32_t)((j * 8 + b_rsub) * 128 + kc * 32 + b_colh);
                ldsm4(bhi, vh + SWZ128(voff));
                ldsm4(blo, vl + SWZ128(voff));
                mma16816(o_acc[j],     ahi, bhi);
                mma16816(o_acc[j],     ahi, blo);
                mma16816(o_acc[j],     alo, bhi);
                mma16816(o_acc[j + 1], ahi, bhi + 2);
                mma16816(o_acc[j + 1], ahi, blo + 2);
                mma16816(o_acc[j + 1], alo, bhi + 2);
            }
        }
        __syncthreads();
    }

    #pragma unroll
    for (int off = 1; off < 4; off <<= 1) {
        lsum0 += __shfl_xor_sync(0xffffffffu, lsum0, off);
        lsum1 += __shfl_xor_sync(0xffffffffu, lsum1, off);
    }
    const float inv0 = 1.0f / lsum0, inv1 = 1.0f / lsum1;

    float* Osm = (float*)smem;
    const int r1 = w * 16 + (lane >> 2);
    const int cb = (lane & 3) << 1;
    #pragma unroll
    for (int nt = 0; nt < 8; nt++) {
        const int c0 = nt * 8 + cb;
        Osm[r1 * 66 + c0]           = o_acc[nt][0] * inv0;
        Osm[r1 * 66 + c0 + 1]       = o_acc[nt][1] * inv0;
        Osm[(r1 + 8) * 66 + c0]     = o_acc[nt][2] * inv1;
        Osm[(r1 + 8) * 66 + c0 + 1] = o_acc[nt][3] * inv1;
    }
    __syncthreads();
    {
        const int dh = tid >> 2;
        const int qc = (tid & 3) << 5;
        float* op = out + ((size_t)b * DD + h * 64 + dh) * LL + q0 + qc;
        #pragma unroll
        for (int i = 0; i < 8; i++) {
            float4 v = make_float4(Osm[(qc + 4 * i + 0) * 66 + dh],
                                   Osm[(qc + 4 * i + 1) * 66 + dh],
                                   Osm[(qc + 4 * i + 2) * 66 + dh],
                                   Osm[(qc + 4 * i + 3) * 66 + dh]);
            *(float4*)(op + 4 * i) = v;
        }
    }
}

// ===========================================================================
extern "C" void kernel_launch(void* const* d_in, const int* in_sizes, int n_in,
                              void* d_out, int out_size) {
    (void)in_sizes; (void)n_in; (void)out_size;
    const float* queries = (const float*)d_in[0];
    const int*   mask    = (const int*)d_in[1];
    const float* w_mem   = (const float*)d_in[2];
    const float* w_q     = (const float*)d_in[3];
    float* out = (float*)d_out;

    cudaFuncSetAttribute(proj_mma, cudaFuncAttributeMaxDynamicSharedMemorySize, P_TOTAL);
    dim3 gp(LL / 128, OT / 128, BB);
    proj_mma<<<gp, 256, P_TOTAL>>>(queries, w_mem, w_q);

    cudaFuncSetAttribute(attn_mma, cudaFuncAttributeMaxDynamicSharedMemorySize, SM_TOTAL);
    dim3 ga(LL / 128, HH, BB);
    attn_mma<<<ga, 256, SM_TOTAL>>>(mask, out);
}

// round 9
// speedup vs baseline: 1.2271x; 1.2271x over previous
#include <cuda_runtime.h>
#include <cuda_fp16.h>
#include <cstdint>
#include <math.h>

#define BB 8
#define DD 512
#define LL 2048
#define HH 8
#define OT 1536

// fp16 scratch, pre-swizzled (SW128 chunk perm by row&7 applied in gmem).
// q: [b][l][512] hi only;  k: [b][l][512] hi/lo;  v: [b][dh 512][l] hi/lo
__device__ __half g_qhi[(size_t)BB * LL * DD];
__device__ __half g_khi[(size_t)BB * LL * DD], g_klo[(size_t)BB * LL * DD];
__device__ __half g_vhi[(size_t)BB * DD * LL], g_vlo[(size_t)BB * DD * LL];

// ============================ helpers ======================================
__device__ __forceinline__ uint32_t smem_u32(const void* p) {
    uint32_t a;
    asm("{ .reg .u64 t; cvta.to.shared.u64 t, %1; cvt.u32.u64 %0, t; }"
        : "=r"(a) : "l"(p));
    return a;
}

#define SWZ128(off) ((off) ^ (((off) >> 3) & 0x70))

__device__ __forceinline__ void ldsm4(uint32_t* r, uint32_t addr) {
    asm volatile("ldmatrix.sync.aligned.m8n8.x4.shared.b16 {%0,%1,%2,%3}, [%4];"
        : "=r"(r[0]), "=r"(r[1]), "=r"(r[2]), "=r"(r[3]) : "r"(addr));
}

__device__ __forceinline__ void ldsm4t(uint32_t* r, uint32_t addr) {
    asm volatile("ldmatrix.sync.aligned.m8n8.x4.trans.shared.b16 {%0,%1,%2,%3}, [%4];"
        : "=r"(r[0]), "=r"(r[1]), "=r"(r[2]), "=r"(r[3]) : "r"(addr));
}

__device__ __forceinline__ void mma16816(float* d, const uint32_t* a, const uint32_t* b) {
    asm volatile("mma.sync.aligned.m16n8k16.row.col.f32.f16.f16.f32 "
        "{%0,%1,%2,%3}, {%4,%5,%6,%7}, {%8,%9}, {%0,%1,%2,%3};"
        : "+f"(d[0]), "+f"(d[1]), "+f"(d[2]), "+f"(d[3])
        : "r"(a[0]), "r"(a[1]), "r"(a[2]), "r"(a[3]), "r"(b[0]), "r"(b[1]));
}

__device__ __forceinline__ void cpa16(uint32_t sdst, const void* gsrc) {
    asm volatile("cp.async.cg.shared.global [%0], [%1], 16;"
        :: "r"(sdst), "l"(gsrc));
}
#define CPA_COMMIT() asm volatile("cp.async.commit_group;" ::: "memory")
#define CPA_WAIT(n)  asm volatile("cp.async.wait_group %0;" :: "n"(n) : "memory")

// fp32x4 -> fp16 hi/lo, store swizzled into smem
__device__ __forceinline__ void cvt_store4_hl(char* smem, uint32_t hi_off, uint32_t lo_off,
                                              uint32_t byte_off, float4 v) {
    __half2 h0, h1, l0, l1;
    h0.x = __float2half_rn(v.x); h0.y = __float2half_rn(v.y);
    h1.x = __float2half_rn(v.z); h1.y = __float2half_rn(v.w);
    l0.x = __float2half_rn(v.x - __half2float(h0.x));
    l0.y = __float2half_rn(v.y - __half2float(h0.y));
    l1.x = __float2half_rn(v.z - __half2float(h1.x));
    l1.y = __float2half_rn(v.w - __half2float(h1.y));
    uint32_t s = SWZ128(byte_off);
    *(__half2*)(smem + hi_off + s)     = h0;
    *(__half2*)(smem + hi_off + s + 4) = h1;
    *(__half2*)(smem + lo_off + s)     = l0;
    *(__half2*)(smem + lo_off + s + 4) = l1;
}

// fp32x4 -> fp16 hi only, store swizzled
__device__ __forceinline__ void cvt_store4_hi(char* smem, uint32_t hi_off,
                                              uint32_t byte_off, float4 v) {
    __half2 h0, h1;
    h0.x = __float2half_rn(v.x); h0.y = __float2half_rn(v.y);
    h1.x = __float2half_rn(v.z); h1.y = __float2half_rn(v.w);
    uint32_t s = SWZ128(byte_off);
    *(__half2*)(smem + hi_off + s)     = h0;
    *(__half2*)(smem + hi_off + s + 4) = h1;
}

// ===========================================================================
// Projection GEMM (tensor pipe, fp16 2-term): out2[o][l] = sum_d W[o][d]*q[d][l]
//   c = W_hi . (x_hi + x_lo)   (omitted W_lo.x ~ 2^-12)
// Epilogue: V -> g_v{hi,lo} [dh][l]; K -> g_k{hi,lo} [l][512]; Q -> g_qhi.
// ===========================================================================
#define PA_HI  0
#define PB0_HI 16384
#define PB0_LO 24576
#define PB1_HI 32768
#define PB1_LO 40960
#define OSTRIDE 132
#define P_TOTAL (128 * OSTRIDE * 4)   // 67584

__global__ __launch_bounds__(256, 2) void proj_mma(
    const float* __restrict__ qin,
    const float* __restrict__ w_mem,
    const float* __restrict__ w_q)
{
    extern __shared__ char smem[];
    const uint32_t sb = smem_u32(smem);
    const int tid = threadIdx.x;
    const int w = tid >> 5, lane = tid & 31;
    const int b  = blockIdx.z;
    const int l0 = blockIdx.x * 128;
    const int o0 = blockIdx.y * 128;

    const float* wptr = (o0 < 1024) ? (w_mem + (size_t)o0 * DD)
                                    : (w_q  + (size_t)(o0 - 1024) * DD);
    const float* qb = qin + (size_t)b * DD * LL;

    const int mi     = lane >> 3;
    const int arow   = w * 16 + ((mi & 1) << 3) + (lane & 7);
    const int acolh  = (mi >> 1) * 16;
    const int b_ksub = ((mi & 1) << 3) + (lane & 7);
    const int b_noct = mi >> 1;

    float c[16][4];
    #pragma unroll
    for (int i = 0; i < 16; i++)
        #pragma unroll
        for (int j = 0; j < 4; j++) c[i][j] = 0.f;

    for (int kc = 0; kc < 8; kc++) {
        __syncthreads();
        // stage A: W[o0..+128][kc*64..+64] hi only
        #pragma unroll
        for (int i = tid; i < 128 * 16; i += 256) {
            int row = i >> 4, d4 = (i & 15) << 2;
            float4 v = *(const float4*)(wptr + (size_t)row * DD + kc * 64 + d4);
            cvt_store4_hi(smem, PA_HI, (uint32_t)(row * 128 + d4 * 2), v);
        }
        // stage B: q[kc*64..+64][l0..+128] hi/lo, two half tiles
        #pragma unroll
        for (int i = tid; i < 64 * 32; i += 256) {
            int row = i >> 5, l4 = (i & 31) << 2;
            float4 v = *(const float4*)(qb + (size_t)(kc * 64 + row) * LL + l0 + l4);
            uint32_t hi = (l4 & 64) ? PB1_HI : PB0_HI;
            uint32_t lo = (l4 & 64) ? PB1_LO : PB0_LO;
            cvt_store4_hl(smem, hi, lo, (uint32_t)(row * 128 + (l4 & 63) * 2), v);
        }
        __syncthreads();

        #pragma unroll
        for (int ks = 0; ks < 4; ks++) {
            uint32_t ahi[4];
            uint32_t aoff = (uint32_t)(arow * 128 + ks * 32 + acolh);
            ldsm4(ahi, sb + PA_HI + SWZ128(aoff));
            #pragma unroll
            for (int hb = 0; hb < 2; hb++) {
                const uint32_t bh = sb + (hb ? PB1_HI : PB0_HI);
                const uint32_t bl = sb + (hb ? PB1_LO : PB0_LO);
                #pragma unroll
                for (int j = 0; j < 8; j += 2) {
                    uint32_t boff = (uint32_t)((ks * 16 + b_ksub) * 128 + (j + b_noct) * 16);
                    uint32_t bhi[4], blo[4];
                    ldsm4t(bhi, bh + SWZ128(boff));
                    ldsm4t(blo, bl + SWZ128(boff));
                    const int o1 = hb * 8 + j;
                    mma16816(c[o1],     ahi, bhi);
                    mma16816(c[o1],     ahi, blo);
                    mma16816(c[o1 + 1], ahi, bhi + 2);
                    mma16816(c[o1 + 1], ahi, blo + 2);
                }
            }
        }
    }

    // ---- fragments -> smem [o][OSTRIDE] fp32 ----
    __syncthreads();
    float* Osm = (float*)smem;
    {
        const int r1 = w * 16 + (lane >> 2);
        const int cb = (lane & 3) << 1;
        #pragma unroll
        for (int oct = 0; oct < 16; oct++) {
            const int col = (oct >> 3) * 64 + (oct & 7) * 8 + cb;
            Osm[r1 * OSTRIDE + col]           = c[oct][0];
            Osm[r1 * OSTRIDE + col + 1]       = c[oct][1];
            Osm[(r1 + 8) * OSTRIDE + col]     = c[oct][2];
            Osm[(r1 + 8) * OSTRIDE + col + 1] = c[oct][3];
        }
    }
    __syncthreads();

    if (o0 >= 512 && o0 < 1024) {
        // V: [dh][l] pre-swizzled hi/lo
        #pragma unroll
        for (int i = tid; i < 2048; i += 256) {
            int row = i >> 4, ch = i & 15;
            int vr = (o0 - 512) + row;
            const float* src = &Osm[row * OSTRIDE + ch * 8];
            __align__(16) __half hi8[8], lo8[8];
            #pragma unroll
            for (int k = 0; k < 8; k++) {
                float x = src[k];
                __half hx = __float2half_rn(x);
                hi8[k] = hx;
                lo8[k] = __float2half_rn(x - __half2float(hx));
            }
            int seg = ch >> 3, pc = (ch & 7) ^ (vr & 7);
            size_t ge = ((size_t)b * DD + vr) * LL + l0 + seg * 64 + pc * 8;
            *(uint4*)&g_vhi[ge] = *(uint4*)hi8;
            *(uint4*)&g_vlo[ge] = *(uint4*)lo8;
        }
    } else if (o0 < 512) {
        // K: transposed [l][512] pre-swizzled hi/lo
        #pragma unroll
        for (int i = tid; i < 2048; i += 256) {
            int l = i >> 4, ch = i & 15;
            int gl = l0 + l;
            __align__(16) __half hi8[8], lo8[8];
            #pragma unroll
            for (int k = 0; k < 8; k++) {
                int rk = (k + lane) & 7;
                float x = Osm[(ch * 8 + rk) * OSTRIDE + l];
                __half hx = __float2half_rn(x);
                hi8[rk] = hx;
                lo8[rk] = __float2half_rn(x - __half2float(hx));
            }
            int seg = ch >> 3, pc = (ch & 7) ^ (gl & 7);
            size_t ge = ((size_t)b * LL + gl) * DD + o0 + seg * 64 + pc * 8;
            *(uint4*)&g_khi[ge] = *(uint4*)hi8;
            *(uint4*)&g_klo[ge] = *(uint4*)lo8;
        }
    } else {
        // Q: transposed [l][512] pre-swizzled, hi only, scaled
        #pragma unroll
        for (int i = tid; i < 2048; i += 256) {
            int l = i >> 4, ch = i & 15;
            int gl = l0 + l;
            __align__(16) __half hi8[8];
            #pragma unroll
            for (int k = 0; k < 8; k++) {
                int rk = (k + lane) & 7;
                hi8[rk] = __float2half_rn(Osm[(ch * 8 + rk) * OSTRIDE + l] * 0.125f);
            }
            int seg = ch >> 3, pc = (ch & 7) ^ (gl & 7);
            size_t ge = ((size_t)b * LL + gl) * DD + (o0 - 1024) + seg * 64 + pc * 8;
            *(uint4*)&g_qhi[ge] = *(uint4*)hi8;
        }
    }
}

// ===========================================================================
// mma.sync flash attention (fp16 2-term), cp.async double-buffered staging.
//   S = Q_hi.(K_hi+K_lo)^T ;  O += P_hi.(V_hi+V_lo)
// ===========================================================================
#define SM_QHI   0
#define ST_BASE  16384
#define ST_SIZE  33024            // KHI 8K | KLO 8K | VHI 8K | VLO 8K | MSK 256
#define SM_TOTAL (ST_BASE + 2 * ST_SIZE)   // 82432

__global__ __launch_bounds__(256, 2) void attn_mma(
    const int* __restrict__ mask, float* __restrict__ out)
{
    extern __shared__ char smem[];
    const uint32_t sb = smem_u32(smem);
    const int tid  = threadIdx.x;
    const int w    = tid >> 5;
    const int lane = tid & 31;
    const int b = blockIdx.z, h = blockIdx.y, q0 = blockIdx.x * 128;

    const size_t qkrow0 = (size_t)b * LL * DD + (size_t)h * 64;   // + l*DD
    const size_t vrow0  = ((size_t)b * DD + h * 64) * LL;         // + dh*LL

    // ---- stage Q hi (group 0, with tile 0) ----
    #pragma unroll
    for (int j = 0; j < 4; j++) {
        int i = tid + j * 256;            // 0..1023
        int row = i >> 3, ch = i & 7;
        cpa16(sb + SM_QHI + row * 128 + ch * 16,
              g_qhi + qkrow0 + (size_t)(q0 + row) * DD + ch * 8);
    }
    // ---- prefetch tile 0 ----
    {
        const uint32_t st = sb + ST_BASE;
        #pragma unroll
        for (int j = 0; j < 2; j++) {
            int i = tid + j * 256;        // 0..511
            int row = i >> 3, ch = i & 7;
            size_t ke = qkrow0 + (size_t)row * DD + ch * 8;
            cpa16(st + row * 128 + ch * 16,         g_khi + ke);
            cpa16(st + 8192 + row * 128 + ch * 16,  g_klo + ke);
            size_t ve = vrow0 + (size_t)row * LL + ch * 8;
            cpa16(st + 16384 + row * 128 + ch * 16, g_vhi + ve);
            cpa16(st + 24576 + row * 128 + ch * 16, g_vlo + ve);
        }
        if (tid < 16) cpa16(st + 32768 + tid * 16, mask + (size_t)b * LL + tid * 4);
    }
    CPA_COMMIT();

    const int mi = lane >> 3;
    const int qrow_l = w * 16 + ((mi & 1) << 3) + (lane & 7);
    const int a_colh = (mi >> 1) * 16;
    const int b_rsub = ((mi >> 1) << 3) + (lane & 7);
    const int b_colh = (mi & 1) * 16;

    float o_acc[8][4];
    #pragma unroll
    for (int i = 0; i < 8; i++)
        #pragma unroll
        for (int j = 0; j < 4; j++) o_acc[i][j] = 0.f;
    float lsum0 = 0.f, lsum1 = 0.f;

    for (int it = 0; it < 32; it++) {
        if (it + 1 < 32) {
            const int k1 = (it + 1) * 64;
            const uint32_t st = sb + ST_BASE + ((it + 1) & 1) * ST_SIZE;
            #pragma unroll
            for (int j = 0; j < 2; j++) {
                int i = tid + j * 256;
                int row = i >> 3, ch = i & 7;
                size_t ke = qkrow0 + (size_t)(k1 + row) * DD + ch * 8;
                cpa16(st + row * 128 + ch * 16,         g_khi + ke);
                cpa16(st + 8192 + row * 128 + ch * 16,  g_klo + ke);
                size_t ve = vrow0 + (size_t)row * LL + k1 + ch * 8;
                cpa16(st + 16384 + row * 128 + ch * 16, g_vhi + ve);
                cpa16(st + 24576 + row * 128 + ch * 16, g_vlo + ve);
            }
            if (tid < 16) cpa16(st + 32768 + tid * 16, mask + (size_t)b * LL + k1 + tid * 4);
            CPA_COMMIT();
            CPA_WAIT(1);
        } else {
            CPA_WAIT(0);
        }
        __syncthreads();

        const uint32_t st = sb + ST_BASE + (it & 1) * ST_SIZE;
        const uint32_t kh = st, kl = st + 8192, vh = st + 16384, vl = st + 24576;
        const int* mp = (const int*)(smem + (ST_BASE + (it & 1) * ST_SIZE + 32768));

        // ---- S = Q_hi.(K_hi+K_lo)^T ----
        float s[8][4];
        #pragma unroll
        for (int i = 0; i < 8; i++)
            #pragma unroll
            for (int j = 0; j < 4; j++) s[i][j] = 0.f;

        #pragma unroll
        for (int kc = 0; kc < 4; kc++) {
            uint32_t ahi[4];
            uint32_t qoff = (uint32_t)(qrow_l * 128 + kc * 32 + a_colh);
            ldsm4(ahi, sb + SM_QHI + SWZ128(qoff));
            #pragma unroll
            for (int j = 0; j < 8; j += 2) {
                uint32_t bhi[4], blo[4];
                uint32_t koff = (uint32_t)((j * 8 + b_rsub) * 128 + kc * 32 + b_colh);
                ldsm4(bhi, kh + SWZ128(koff));
                ldsm4(blo, kl + SWZ128(koff));
                mma16816(s[j],     ahi, bhi);
                mma16816(s[j],     ahi, blo);
                mma16816(s[j + 1], ahi, bhi + 2);
                mma16816(s[j + 1], ahi, blo + 2);
            }
        }

        // ---- softmax + P_hi packing ----
        uint32_t phiA[8], phiB[8];
        #pragma unroll
        for (int nt = 0; nt < 8; nt++) {
            const int c0 = nt * 8 + ((lane & 3) << 1);
            const bool m0v = mp[c0] != 0, m1v = mp[c0 + 1] != 0;
            float p0 = m0v ? __expf(s[nt][0]) : 0.f;
            float p1 = m1v ? __expf(s[nt][1]) : 0.f;
            float p2 = m0v ? __expf(s[nt][2]) : 0.f;
            float p3 = m1v ? __expf(s[nt][3]) : 0.f;
            lsum0 += p0 + p1;
            lsum1 += p2 + p3;
            __half2 hA, hB;
            hA.x = __float2half_rn(p0); hA.y = __float2half_rn(p1);
            hB.x = __float2half_rn(p2); hB.y = __float2half_rn(p3);
            phiA[nt] = *(uint32_t*)&hA; phiB[nt] = *(uint32_t*)&hB;
        }

        // ---- O += P_hi.(V_hi+V_lo) ----
        #pragma unroll
        for (int kc = 0; kc < 4; kc++) {
            uint32_t ahi[4] = {phiA[2 * kc], phiB[2 * kc], phiA[2 * kc + 1], phiB[2 * kc + 1]};
            #pragma unroll
            for (int j = 0; j < 8; j += 2) {
                uint32_t bhi[4], blo[4];
                uint32_t voff = (uint32_t)((j * 8 + b_rsub) * 128 + kc * 32 + b_colh);
                ldsm4(bhi, vh + SWZ128(voff));
                ldsm4(blo, vl + SWZ128(voff));
                mma16816(o_acc[j],     ahi, bhi);
                mma16816(o_acc[j],     ahi, blo);
                mma16816(o_acc[j + 1], ahi, bhi + 2);
                mma16816(o_acc[j + 1], ahi, blo + 2);
            }
        }
        __syncthreads();
    }

    #pragma unroll
    for (int off = 1; off < 4; off <<= 1) {
        lsum0 += __shfl_xor_sync(0xffffffffu, lsum0, off);
        lsum1 += __shfl_xor_sync(0xffffffffu, lsum1, off);
    }
    const float inv0 = 1.0f / lsum0, inv1 = 1.0f / lsum1;

    float* Osm = (float*)smem;
    const int r1 = w * 16 + (lane >> 2);
    const int cb = (lane & 3) << 1;
    #pragma unroll
    for (int nt = 0; nt < 8; nt++) {
        const int c0 = nt * 8 + cb;
        Osm[r1 * 66 + c0]           = o_acc[nt][0] * inv0;
        Osm[r1 * 66 + c0 + 1]       = o_acc[nt][1] * inv0;
        Osm[(r1 + 8) * 66 + c0]     = o_acc[nt][2] * inv1;
        Osm[(r1 + 8) * 66 + c0 + 1] = o_acc[nt][3] * inv1;
    }
    __syncthreads();
    {
        const int dh = tid >> 2;
        const int qc = (tid & 3) << 5;
        float* op = out + ((size_t)b * DD + h * 64 + dh) * LL + q0 + qc;
        #pragma unroll
        for (int i = 0; i < 8; i++) {
            float4 v = make_float4(Osm[(qc + 4 * i + 0) * 66 + dh],
                                   Osm[(qc + 4 * i + 1) * 66 + dh],
                                   Osm[(qc + 4 * i + 2) * 66 + dh],
                                   Osm[(qc + 4 * i + 3) * 66 + dh]);
            *(float4*)(op + 4 * i) = v;
        }
    }
}

// ===========================================================================
extern "C" void kernel_launch(void* const* d_in, const int* in_sizes, int n_in,
                              void* d_out, int out_size) {
    (void)in_sizes; (void)n_in; (void)out_size;
    const float* queries = (const float*)d_in[0];
    const int*   mask    = (const int*)d_in[1];
    const float* w_mem   = (const float*)d_in[2];
    const float* w_q     = (const float*)d_in[3];
    float* out = (float*)d_out;

    cudaFuncSetAttribute(proj_mma, cudaFuncAttributeMaxDynamicSharedMemorySize, P_TOTAL);
    dim3 gp(LL / 128, OT / 128, BB);
    proj_mma<<<gp, 256, P_TOTAL>>>(queries, w_mem, w_q);

    cudaFuncSetAttribute(attn_mma, cudaFuncAttributeMaxDynamicSharedMemorySize, SM_TOTAL);
    dim3 ga(LL / 128, HH, BB);
    attn_mma<<<ga, 256, SM_TOTAL>>>(mask, out);
}

// round 10
// speedup vs baseline: 1.2455x; 1.0150x over previous
#include <cuda_runtime.h>
#include <cuda_fp16.h>
#include <cstdint>
#include <math.h>

#define BB 8
#define DD 512
#define LL 2048
#define HH 8
#define OT 1536

// fp16 scratch, pre-swizzled (SW128 chunk perm by row&7 applied in gmem).
// q: [b][l][512] hi only;  k: [b][l][512] hi/lo;  v: [b][dh 512][l] hi/lo
__device__ __half g_qhi[(size_t)BB * LL * DD];
__device__ __half g_khi[(size_t)BB * LL * DD], g_klo[(size_t)BB * LL * DD];
__device__ __half g_vhi[(size_t)BB * DD * LL], g_vlo[(size_t)BB * DD * LL];

// ============================ helpers ======================================
__device__ __forceinline__ uint32_t smem_u32(const void* p) {
    uint32_t a;
    asm("{ .reg .u64 t; cvta.to.shared.u64 t, %1; cvt.u32.u64 %0, t; }"
        : "=r"(a) : "l"(p));
    return a;
}

#define SWZ128(off) ((off) ^ (((off) >> 3) & 0x70))

__device__ __forceinline__ void ldsm4(uint32_t* r, uint32_t addr) {
    asm volatile("ldmatrix.sync.aligned.m8n8.x4.shared.b16 {%0,%1,%2,%3}, [%4];"
        : "=r"(r[0]), "=r"(r[1]), "=r"(r[2]), "=r"(r[3]) : "r"(addr));
}

__device__ __forceinline__ void ldsm4t(uint32_t* r, uint32_t addr) {
    asm volatile("ldmatrix.sync.aligned.m8n8.x4.trans.shared.b16 {%0,%1,%2,%3}, [%4];"
        : "=r"(r[0]), "=r"(r[1]), "=r"(r[2]), "=r"(r[3]) : "r"(addr));
}

__device__ __forceinline__ void mma16816(float* d, const uint32_t* a, const uint32_t* b) {
    asm volatile("mma.sync.aligned.m16n8k16.row.col.f32.f16.f16.f32 "
        "{%0,%1,%2,%3}, {%4,%5,%6,%7}, {%8,%9}, {%0,%1,%2,%3};"
        : "+f"(d[0]), "+f"(d[1]), "+f"(d[2]), "+f"(d[3])
        : "r"(a[0]), "r"(a[1]), "r"(a[2]), "r"(a[3]), "r"(b[0]), "r"(b[1]));
}

__device__ __forceinline__ void cpa16(uint32_t sdst, const void* gsrc) {
    asm volatile("cp.async.cg.shared.global [%0], [%1], 16;"
        :: "r"(sdst), "l"(gsrc));
}
#define CPA_COMMIT() asm volatile("cp.async.commit_group;" ::: "memory")
#define CPA_WAIT(n)  asm volatile("cp.async.wait_group %0;" :: "n"(n) : "memory")

// fp32x4 -> fp16 hi/lo, store swizzled into smem
__device__ __forceinline__ void cvt_store4_hl(char* smem, uint32_t hi_off, uint32_t lo_off,
                                              uint32_t byte_off, float4 v) {
    __half2 h0, h1, l0, l1;
    h0.x = __float2half_rn(v.x); h0.y = __float2half_rn(v.y);
    h1.x = __float2half_rn(v.z); h1.y = __float2half_rn(v.w);
    l0.x = __float2half_rn(v.x - __half2float(h0.x));
    l0.y = __float2half_rn(v.y - __half2float(h0.y));
    l1.x = __float2half_rn(v.z - __half2float(h1.x));
    l1.y = __float2half_rn(v.w - __half2float(h1.y));
    uint32_t s = SWZ128(byte_off);
    *(__half2*)(smem + hi_off + s)     = h0;
    *(__half2*)(smem + hi_off + s + 4) = h1;
    *(__half2*)(smem + lo_off + s)     = l0;
    *(__half2*)(smem + lo_off + s + 4) = l1;
}

// fp32x4 -> fp16 hi only, store swizzled
__device__ __forceinline__ void cvt_store4_hi(char* smem, uint32_t hi_off,
                                              uint32_t byte_off, float4 v) {
    __half2 h0, h1;
    h0.x = __float2half_rn(v.x); h0.y = __float2half_rn(v.y);
    h1.x = __float2half_rn(v.z); h1.y = __float2half_rn(v.w);
    uint32_t s = SWZ128(byte_off);
    *(__half2*)(smem + hi_off + s)     = h0;
    *(__half2*)(smem + hi_off + s + 4) = h1;
}

// ===========================================================================
// Projection GEMM (unchanged from Round 9, validated)
// ===========================================================================
#define PA_HI  0
#define PB0_HI 16384
#define PB0_LO 24576
#define PB1_HI 32768
#define PB1_LO 40960
#define OSTRIDE 132
#define P_TOTAL (128 * OSTRIDE * 4)   // 67584

__global__ __launch_bounds__(256, 2) void proj_mma(
    const float* __restrict__ qin,
    const float* __restrict__ w_mem,
    const float* __restrict__ w_q)
{
    extern __shared__ char smem[];
    const uint32_t sb = smem_u32(smem);
    const int tid = threadIdx.x;
    const int w = tid >> 5, lane = tid & 31;
    const int b  = blockIdx.z;
    const int l0 = blockIdx.x * 128;
    const int o0 = blockIdx.y * 128;

    const float* wptr = (o0 < 1024) ? (w_mem + (size_t)o0 * DD)
                                    : (w_q  + (size_t)(o0 - 1024) * DD);
    const float* qb = qin + (size_t)b * DD * LL;

    const int mi     = lane >> 3;
    const int arow   = w * 16 + ((mi & 1) << 3) + (lane & 7);
    const int acolh  = (mi >> 1) * 16;
    const int b_ksub = ((mi & 1) << 3) + (lane & 7);
    const int b_noct = mi >> 1;

    float c[16][4];
    #pragma unroll
    for (int i = 0; i < 16; i++)
        #pragma unroll
        for (int j = 0; j < 4; j++) c[i][j] = 0.f;

    for (int kc = 0; kc < 8; kc++) {
        __syncthreads();
        #pragma unroll
        for (int i = tid; i < 128 * 16; i += 256) {
            int row = i >> 4, d4 = (i & 15) << 2;
            float4 v = *(const float4*)(wptr + (size_t)row * DD + kc * 64 + d4);
            cvt_store4_hi(smem, PA_HI, (uint32_t)(row * 128 + d4 * 2), v);
        }
        #pragma unroll
        for (int i = tid; i < 64 * 32; i += 256) {
            int row = i >> 5, l4 = (i & 31) << 2;
            float4 v = *(const float4*)(qb + (size_t)(kc * 64 + row) * LL + l0 + l4);
            uint32_t hi = (l4 & 64) ? PB1_HI : PB0_HI;
            uint32_t lo = (l4 & 64) ? PB1_LO : PB0_LO;
            cvt_store4_hl(smem, hi, lo, (uint32_t)(row * 128 + (l4 & 63) * 2), v);
        }
        __syncthreads();

        #pragma unroll
        for (int ks = 0; ks < 4; ks++) {
            uint32_t ahi[4];
            uint32_t aoff = (uint32_t)(arow * 128 + ks * 32 + acolh);
            ldsm4(ahi, sb + PA_HI + SWZ128(aoff));
            #pragma unroll
            for (int hb = 0; hb < 2; hb++) {
                const uint32_t bh = sb + (hb ? PB1_HI : PB0_HI);
                const uint32_t bl = sb + (hb ? PB1_LO : PB0_LO);
                #pragma unroll
                for (int j = 0; j < 8; j += 2) {
                    uint32_t boff = (uint32_t)((ks * 16 + b_ksub) * 128 + (j + b_noct) * 16);
                    uint32_t bhi[4], blo[4];
                    ldsm4t(bhi, bh + SWZ128(boff));
                    ldsm4t(blo, bl + SWZ128(boff));
                    const int o1 = hb * 8 + j;
                    mma16816(c[o1],     ahi, bhi);
                    mma16816(c[o1],     ahi, blo);
                    mma16816(c[o1 + 1], ahi, bhi + 2);
                    mma16816(c[o1 + 1], ahi, blo + 2);
                }
            }
        }
    }

    __syncthreads();
    float* Osm = (float*)smem;
    {
        const int r1 = w * 16 + (lane >> 2);
        const int cb = (lane & 3) << 1;
        #pragma unroll
        for (int oct = 0; oct < 16; oct++) {
            const int col = (oct >> 3) * 64 + (oct & 7) * 8 + cb;
            Osm[r1 * OSTRIDE + col]           = c[oct][0];
            Osm[r1 * OSTRIDE + col + 1]       = c[oct][1];
            Osm[(r1 + 8) * OSTRIDE + col]     = c[oct][2];
            Osm[(r1 + 8) * OSTRIDE + col + 1] = c[oct][3];
        }
    }
    __syncthreads();

    if (o0 >= 512 && o0 < 1024) {
        #pragma unroll
        for (int i = tid; i < 2048; i += 256) {
            int row = i >> 4, ch = i & 15;
            int vr = (o0 - 512) + row;
            const float* src = &Osm[row * OSTRIDE + ch * 8];
            __align__(16) __half hi8[8], lo8[8];
            #pragma unroll
            for (int k = 0; k < 8; k++) {
                float x = src[k];
                __half hx = __float2half_rn(x);
                hi8[k] = hx;
                lo8[k] = __float2half_rn(x - __half2float(hx));
            }
            int seg = ch >> 3, pc = (ch & 7) ^ (vr & 7);
            size_t ge = ((size_t)b * DD + vr) * LL + l0 + seg * 64 + pc * 8;
            *(uint4*)&g_vhi[ge] = *(uint4*)hi8;
            *(uint4*)&g_vlo[ge] = *(uint4*)lo8;
        }
    } else if (o0 < 512) {
        #pragma unroll
        for (int i = tid; i < 2048; i += 256) {
            int l = i >> 4, ch = i & 15;
            int gl = l0 + l;
            __align__(16) __half hi8[8], lo8[8];
            #pragma unroll
            for (int k = 0; k < 8; k++) {
                int rk = (k + lane) & 7;
                float x = Osm[(ch * 8 + rk) * OSTRIDE + l];
                __half hx = __float2half_rn(x);
                hi8[rk] = hx;
                lo8[rk] = __float2half_rn(x - __half2float(hx));
            }
            int seg = ch >> 3, pc = (ch & 7) ^ (gl & 7);
            size_t ge = ((size_t)b * LL + gl) * DD + o0 + seg * 64 + pc * 8;
            *(uint4*)&g_khi[ge] = *(uint4*)hi8;
            *(uint4*)&g_klo[ge] = *(uint4*)lo8;
        }
    } else {
        #pragma unroll
        for (int i = tid; i < 2048; i += 256) {
            int l = i >> 4, ch = i & 15;
            int gl = l0 + l;
            __align__(16) __half hi8[8];
            #pragma unroll
            for (int k = 0; k < 8; k++) {
                int rk = (k + lane) & 7;
                hi8[rk] = __float2half_rn(Osm[(ch * 8 + rk) * OSTRIDE + l] * 0.125f);
            }
            int seg = ch >> 3, pc = (ch & 7) ^ (gl & 7);
            size_t ge = ((size_t)b * LL + gl) * DD + (o0 - 1024) + seg * 64 + pc * 8;
            *(uint4*)&g_qhi[ge] = *(uint4*)hi8;
        }
    }
}

// ===========================================================================
// mma.sync flash attention: Q frags in registers, triple-buffered cp.async
// staging (2-deep prefetch), ONE __syncthreads per iteration, incremental
// gmem pointers (no per-iter 64-bit address math).
// ===========================================================================
#define ST_SIZE  33024            // KHI 8K | KLO 8K | VHI 8K | VLO 8K | MSK 256
#define SM_TOTAL (3 * ST_SIZE)    // 99072

__global__ __launch_bounds__(256, 2) void attn_mma(
    const int* __restrict__ mask, float* __restrict__ out)
{
    extern __shared__ char smem[];
    const uint32_t sb = smem_u32(smem);
    const int tid  = threadIdx.x;
    const int w    = tid >> 5;
    const int lane = tid & 31;
    const int b = blockIdx.z, h = blockIdx.y, q0 = blockIdx.x * 128;

    const size_t qkrow0 = (size_t)b * LL * DD + (size_t)h * 64;   // + l*DD
    const size_t vrow0  = ((size_t)b * DD + h * 64) * LL;         // + dh*LL

    // staging geometry: thread copies rows {srow, srow+32} (j=0,1), chunk sch
    const int srow = tid >> 3;         // 0..31
    const int sch  = tid & 7;
    const uint32_t sd = (uint32_t)(srow * 128 + sch * 16);

    // incremental gmem pointers (advance per tile)
    const __half* pkh = g_khi + qkrow0 + (size_t)srow * DD + sch * 8;
    const __half* pkl = g_klo + qkrow0 + (size_t)srow * DD + sch * 8;
    const __half* pvh = g_vhi + vrow0 + (size_t)srow * LL + sch * 8;
    const __half* pvl = g_vlo + vrow0 + (size_t)srow * LL + sch * 8;
    const int*    pmk = mask + (size_t)b * LL + tid * 4;

#define PREFETCH_TILE(stb) do { \
    cpa16((stb) + sd,                 pkh); \
    cpa16((stb) + sd + 4096,          pkh + 32 * DD); \
    cpa16((stb) + 8192  + sd,         pkl); \
    cpa16((stb) + 8192  + sd + 4096,  pkl + 32 * DD); \
    cpa16((stb) + 16384 + sd,         pvh); \
    cpa16((stb) + 16384 + sd + 4096,  pvh + (size_t)32 * LL); \
    cpa16((stb) + 24576 + sd,         pvl); \
    cpa16((stb) + 24576 + sd + 4096,  pvl + (size_t)32 * LL); \
    if (tid < 16) cpa16((stb) + 32768 + tid * 16, pmk); \
    pkh += 64 * DD; pkl += 64 * DD; pvh += 64; pvl += 64; pmk += 64; \
} while (0)

    // ---- group 1: Q (128 rows) into buf2 region ----
    {
        const __half* pq = g_qhi + qkrow0 + (size_t)(q0 + srow) * DD + sch * 8;
        const uint32_t qst = sb + 2 * ST_SIZE;
        cpa16(qst + sd,          pq);
        cpa16(qst + sd + 4096,   pq + 32 * DD);
        cpa16(qst + sd + 8192,   pq + 64 * DD);
        cpa16(qst + sd + 12288,  pq + 96 * DD);
        CPA_COMMIT();
    }
    // ---- groups 2,3: tiles 0,1 ----
    PREFETCH_TILE(sb);             CPA_COMMIT();
    PREFETCH_TILE(sb + ST_SIZE);   CPA_COMMIT();

    const int mi = lane >> 3;
    const int qrow_l = w * 16 + ((mi & 1) << 3) + (lane & 7);
    const int a_colh = (mi >> 1) * 16;
    const int b_rsub = ((mi >> 1) << 3) + (lane & 7);
    const int b_colh = (mi & 1) * 16;

    // ---- extract Q fragments into registers (Q smem never touched again) ----
    CPA_WAIT(2);
    __syncthreads();
    uint32_t qf[4][4];
    {
        const uint32_t qb2 = sb + 2 * ST_SIZE;
        #pragma unroll
        for (int kc = 0; kc < 4; kc++) {
            uint32_t qoff = (uint32_t)(qrow_l * 128 + kc * 32 + a_colh);
            ldsm4(qf[kc], qb2 + SWZ128(qoff));
        }
    }
    __syncthreads();   // Q frags extracted before iter0 prefetch clobbers buf2

    float o_acc[8][4];
    #pragma unroll
    for (int i = 0; i < 8; i++)
        #pragma unroll
        for (int j = 0; j < 4; j++) o_acc[i][j] = 0.f;
    float lsum0 = 0.f, lsum1 = 0.f;

    uint32_t stc = sb;          // buffer holding current tile (it % 3)
    uint32_t stn = sb + 2 * ST_SIZE;   // buffer for tile it+2

    for (int it = 0; it < 32; it++) {
        if (it == 31) { CPA_WAIT(0); } else { CPA_WAIT(1); }
        __syncthreads();        // publishes tile it; licenses clobber of buf (it-1)%3

        if (it + 2 < 32) {
            PREFETCH_TILE(stn);
            CPA_COMMIT();
            stn = (stn == sb + 2 * ST_SIZE) ? sb : stn + ST_SIZE;
        }

        const uint32_t kh = stc, kl = stc + 8192, vh = stc + 16384, vl = stc + 24576;
        const int* mp = (const int*)(smem + (stc - sb) + 32768);

        // ---- S = Q_hi.(K_hi+K_lo)^T ----
        float s[8][4];
        #pragma unroll
        for (int i = 0; i < 8; i++)
            #pragma unroll
            for (int j = 0; j < 4; j++) s[i][j] = 0.f;

        #pragma unroll
        for (int kc = 0; kc < 4; kc++) {
            #pragma unroll
            for (int j = 0; j < 8; j += 2) {
                uint32_t bhi[4], blo[4];
                uint32_t koff = (uint32_t)((j * 8 + b_rsub) * 128 + kc * 32 + b_colh);
                ldsm4(bhi, kh + SWZ128(koff));
                ldsm4(blo, kl + SWZ128(koff));
                mma16816(s[j],     qf[kc], bhi);
                mma16816(s[j],     qf[kc], blo);
                mma16816(s[j + 1], qf[kc], bhi + 2);
                mma16816(s[j + 1], qf[kc], blo + 2);
            }
        }

        // ---- softmax + P_hi packing ----
        uint32_t phiA[8], phiB[8];
        #pragma unroll
        for (int nt = 0; nt < 8; nt++) {
            const int c0 = nt * 8 + ((lane & 3) << 1);
            const bool m0v = mp[c0] != 0, m1v = mp[c0 + 1] != 0;
            float p0 = m0v ? __expf(s[nt][0]) : 0.f;
            float p1 = m1v ? __expf(s[nt][1]) : 0.f;
            float p2 = m0v ? __expf(s[nt][2]) : 0.f;
            float p3 = m1v ? __expf(s[nt][3]) : 0.f;
            lsum0 += p0 + p1;
            lsum1 += p2 + p3;
            __half2 hA, hB;
            hA.x = __float2half_rn(p0); hA.y = __float2half_rn(p1);
            hB.x = __float2half_rn(p2); hB.y = __float2half_rn(p3);
            phiA[nt] = *(uint32_t*)&hA; phiB[nt] = *(uint32_t*)&hB;
        }

        // ---- O += P_hi.(V_hi+V_lo) ----
        #pragma unroll
        for (int kc = 0; kc < 4; kc++) {
            uint32_t ahi[4] = {phiA[2 * kc], phiB[2 * kc], phiA[2 * kc + 1], phiB[2 * kc + 1]};
            #pragma unroll
            for (int j = 0; j < 8; j += 2) {
                uint32_t bhi[4], blo[4];
                uint32_t voff = (uint32_t)((j * 8 + b_rsub) * 128 + kc * 32 + b_colh);
                ldsm4(bhi, vh + SWZ128(voff));
                ldsm4(blo, vl + SWZ128(voff));
                mma16816(o_acc[j],     ahi, bhi);
                mma16816(o_acc[j],     ahi, blo);
                mma16816(o_acc[j + 1], ahi, bhi + 2);
                mma16816(o_acc[j + 1], ahi, blo + 2);
            }
        }

        stc = (stc == sb + 2 * ST_SIZE) ? sb : stc + ST_SIZE;
    }

    __syncthreads();   // all tile reads done before smem reuse as Osm

    #pragma unroll
    for (int off = 1; off < 4; off <<= 1) {
        lsum0 += __shfl_xor_sync(0xffffffffu, lsum0, off);
        lsum1 += __shfl_xor_sync(0xffffffffu, lsum1, off);
    }
    const float inv0 = 1.0f / lsum0, inv1 = 1.0f / lsum1;

    float* Osm = (float*)smem;
    const int r1 = w * 16 + (lane >> 2);
    const int cb = (lane & 3) << 1;
    #pragma unroll
    for (int nt = 0; nt < 8; nt++) {
        const int c0 = nt * 8 + cb;
        Osm[r1 * 66 + c0]           = o_acc[nt][0] * inv0;
        Osm[r1 * 66 + c0 + 1]       = o_acc[nt][1] * inv0;
        Osm[(r1 + 8) * 66 + c0]     = o_acc[nt][2] * inv1;
        Osm[(r1 + 8) * 66 + c0 + 1] = o_acc[nt][3] * inv1;
    }
    __syncthreads();
    {
        const int dh = tid >> 2;
        const int qc = (tid & 3) << 5;
        float* op = out + ((size_t)b * DD + h * 64 + dh) * LL + q0 + qc;
        #pragma unroll
        for (int i = 0; i < 8; i++) {
            float4 v = make_float4(Osm[(qc + 4 * i + 0) * 66 + dh],
                                   Osm[(qc + 4 * i + 1) * 66 + dh],
                                   Osm[(qc + 4 * i + 2) * 66 + dh],
                                   Osm[(qc + 4 * i + 3) * 66 + dh]);
            *(float4*)(op + 4 * i) = v;
        }
    }
}

// ===========================================================================
extern "C" void kernel_launch(void* const* d_in, const int* in_sizes, int n_in,
                              void* d_out, int out_size) {
    (void)in_sizes; (void)n_in; (void)out_size;
    const float* queries = (const float*)d_in[0];
    const int*   mask    = (const int*)d_in[1];
    const float* w_mem   = (const float*)d_in[2];
    const float* w_q     = (const float*)d_in[3];
    float* out = (float*)d_out;

    cudaFuncSetAttribute(proj_mma, cudaFuncAttributeMaxDynamicSharedMemorySize, P_TOTAL);
    dim3 gp(LL / 128, OT / 128, BB);
    proj_mma<<<gp, 256, P_TOTAL>>>(queries, w_mem, w_q);

    cudaFuncSetAttribute(attn_mma, cudaFuncAttributeMaxDynamicSharedMemorySize, SM_TOTAL);
    dim3 ga(LL / 128, HH, BB);
    attn_mma<<<ga, 256, SM_TOTAL>>>(mask, out);
}

// round 11
// speedup vs baseline: 1.6075x; 1.2907x over previous
#include <cuda_runtime.h>
#include <cuda_fp16.h>
#include <cstdint>
#include <math.h>

#define BB 8
#define DD 512
#define LL 2048
#define HH 8
#define OT 1536

// fp16 scratch, pre-swizzled (SW128 chunk perm by row&7 applied in gmem).
// q,k: [b][l][512] hi only;  v: [b][dh 512][l] hi only
__device__ __half g_qhi[(size_t)BB * LL * DD];
__device__ __half g_khi[(size_t)BB * LL * DD];
__device__ __half g_vhi[(size_t)BB * DD * LL];

// ============================ helpers ======================================
__device__ __forceinline__ uint32_t smem_u32(const void* p) {
    uint32_t a;
    asm("{ .reg .u64 t; cvta.to.shared.u64 t, %1; cvt.u32.u64 %0, t; }"
        : "=r"(a) : "l"(p));
    return a;
}

#define SWZ128(off) ((off) ^ (((off) >> 3) & 0x70))

__device__ __forceinline__ void ldsm4(uint32_t* r, uint32_t addr) {
    asm volatile("ldmatrix.sync.aligned.m8n8.x4.shared.b16 {%0,%1,%2,%3}, [%4];"
        : "=r"(r[0]), "=r"(r[1]), "=r"(r[2]), "=r"(r[3]) : "r"(addr));
}

__device__ __forceinline__ void ldsm4t(uint32_t* r, uint32_t addr) {
    asm volatile("ldmatrix.sync.aligned.m8n8.x4.trans.shared.b16 {%0,%1,%2,%3}, [%4];"
        : "=r"(r[0]), "=r"(r[1]), "=r"(r[2]), "=r"(r[3]) : "r"(addr));
}

__device__ __forceinline__ void mma16816(float* d, const uint32_t* a, const uint32_t* b) {
    asm volatile("mma.sync.aligned.m16n8k16.row.col.f32.f16.f16.f32 "
        "{%0,%1,%2,%3}, {%4,%5,%6,%7}, {%8,%9}, {%0,%1,%2,%3};"
        : "+f"(d[0]), "+f"(d[1]), "+f"(d[2]), "+f"(d[3])
        : "r"(a[0]), "r"(a[1]), "r"(a[2]), "r"(a[3]), "r"(b[0]), "r"(b[1]));
}

__device__ __forceinline__ void cpa16(uint32_t sdst, const void* gsrc) {
    asm volatile("cp.async.cg.shared.global [%0], [%1], 16;"
        :: "r"(sdst), "l"(gsrc));
}
#define CPA_COMMIT() asm volatile("cp.async.commit_group;" ::: "memory")
#define CPA_WAIT(n)  asm volatile("cp.async.wait_group %0;" :: "n"(n) : "memory")

// fp32x4 -> fp16 hi/lo, store swizzled into smem
__device__ __forceinline__ void cvt_store4_hl(char* smem, uint32_t hi_off, uint32_t lo_off,
                                              uint32_t byte_off, float4 v) {
    __half2 h0, h1, l0, l1;
    h0.x = __float2half_rn(v.x); h0.y = __float2half_rn(v.y);
    h1.x = __float2half_rn(v.z); h1.y = __float2half_rn(v.w);
    l0.x = __float2half_rn(v.x - __half2float(h0.x));
    l0.y = __float2half_rn(v.y - __half2float(h0.y));
    l1.x = __float2half_rn(v.z - __half2float(h1.x));
    l1.y = __float2half_rn(v.w - __half2float(h1.y));
    uint32_t s = SWZ128(byte_off);
    *(__half2*)(smem + hi_off + s)     = h0;
    *(__half2*)(smem + hi_off + s + 4) = h1;
    *(__half2*)(smem + lo_off + s)     = l0;
    *(__half2*)(smem + lo_off + s + 4) = l1;
}

// fp32x4 -> fp16 hi only, store swizzled
__device__ __forceinline__ void cvt_store4_hi(char* smem, uint32_t hi_off,
                                              uint32_t byte_off, float4 v) {
    __half2 h0, h1;
    h0.x = __float2half_rn(v.x); h0.y = __float2half_rn(v.y);
    h1.x = __float2half_rn(v.z); h1.y = __float2half_rn(v.w);
    uint32_t s = SWZ128(byte_off);
    *(__half2*)(smem + hi_off + s)     = h0;
    *(__half2*)(smem + hi_off + s + 4) = h1;
}

// ===========================================================================
// Projection GEMM (tensor pipe, fp16 2-term): out2[o][l] = sum_d W[o][d]*q[d][l]
// Epilogue: all outputs stored fp16 hi-only, pre-swizzled.
// ===========================================================================
#define PA_HI  0
#define PB0_HI 16384
#define PB0_LO 24576
#define PB1_HI 32768
#define PB1_LO 40960
#define OSTRIDE 132
#define P_TOTAL (128 * OSTRIDE * 4)   // 67584

__global__ __launch_bounds__(256, 2) void proj_mma(
    const float* __restrict__ qin,
    const float* __restrict__ w_mem,
    const float* __restrict__ w_q)
{
    extern __shared__ char smem[];
    const uint32_t sb = smem_u32(smem);
    const int tid = threadIdx.x;
    const int w = tid >> 5, lane = tid & 31;
    const int b  = blockIdx.z;
    const int l0 = blockIdx.x * 128;
    const int o0 = blockIdx.y * 128;

    const float* wptr = (o0 < 1024) ? (w_mem + (size_t)o0 * DD)
                                    : (w_q  + (size_t)(o0 - 1024) * DD);
    const float* qb = qin + (size_t)b * DD * LL;

    const int mi     = lane >> 3;
    const int arow   = w * 16 + ((mi & 1) << 3) + (lane & 7);
    const int acolh  = (mi >> 1) * 16;
    const int b_ksub = ((mi & 1) << 3) + (lane & 7);
    const int b_noct = mi >> 1;

    float c[16][4];
    #pragma unroll
    for (int i = 0; i < 16; i++)
        #pragma unroll
        for (int j = 0; j < 4; j++) c[i][j] = 0.f;

    for (int kc = 0; kc < 8; kc++) {
        __syncthreads();
        #pragma unroll
        for (int i = tid; i < 128 * 16; i += 256) {
            int row = i >> 4, d4 = (i & 15) << 2;
            float4 v = *(const float4*)(wptr + (size_t)row * DD + kc * 64 + d4);
            cvt_store4_hi(smem, PA_HI, (uint32_t)(row * 128 + d4 * 2), v);
        }
        #pragma unroll
        for (int i = tid; i < 64 * 32; i += 256) {
            int row = i >> 5, l4 = (i & 31) << 2;
            float4 v = *(const float4*)(qb + (size_t)(kc * 64 + row) * LL + l0 + l4);
            uint32_t hi = (l4 & 64) ? PB1_HI : PB0_HI;
            uint32_t lo = (l4 & 64) ? PB1_LO : PB0_LO;
            cvt_store4_hl(smem, hi, lo, (uint32_t)(row * 128 + (l4 & 63) * 2), v);
        }
        __syncthreads();

        #pragma unroll
        for (int ks = 0; ks < 4; ks++) {
            uint32_t ahi[4];
            uint32_t aoff = (uint32_t)(arow * 128 + ks * 32 + acolh);
            ldsm4(ahi, sb + PA_HI + SWZ128(aoff));
            #pragma unroll
            for (int hb = 0; hb < 2; hb++) {
                const uint32_t bh = sb + (hb ? PB1_HI : PB0_HI);
                const uint32_t bl = sb + (hb ? PB1_LO : PB0_LO);
                #pragma unroll
                for (int j = 0; j < 8; j += 2) {
                    uint32_t boff = (uint32_t)((ks * 16 + b_ksub) * 128 + (j + b_noct) * 16);
                    uint32_t bhi[4], blo[4];
                    ldsm4t(bhi, bh + SWZ128(boff));
                    ldsm4t(blo, bl + SWZ128(boff));
                    const int o1 = hb * 8 + j;
                    mma16816(c[o1],     ahi, bhi);
                    mma16816(c[o1],     ahi, blo);
                    mma16816(c[o1 + 1], ahi, bhi + 2);
                    mma16816(c[o1 + 1], ahi, blo + 2);
                }
            }
        }
    }

    __syncthreads();
    float* Osm = (float*)smem;
    {
        const int r1 = w * 16 + (lane >> 2);
        const int cb = (lane & 3) << 1;
        #pragma unroll
        for (int oct = 0; oct < 16; oct++) {
            const int col = (oct >> 3) * 64 + (oct & 7) * 8 + cb;
            Osm[r1 * OSTRIDE + col]           = c[oct][0];
            Osm[r1 * OSTRIDE + col + 1]       = c[oct][1];
            Osm[(r1 + 8) * OSTRIDE + col]     = c[oct][2];
            Osm[(r1 + 8) * OSTRIDE + col + 1] = c[oct][3];
        }
    }
    __syncthreads();

    if (o0 >= 512 && o0 < 1024) {
        // V: [dh][l] pre-swizzled, hi only
        #pragma unroll
        for (int i = tid; i < 2048; i += 256) {
            int row = i >> 4, ch = i & 15;
            int vr = (o0 - 512) + row;
            const float* src = &Osm[row * OSTRIDE + ch * 8];
            __align__(16) __half hi8[8];
            #pragma unroll
            for (int k = 0; k < 8; k++)
                hi8[k] = __float2half_rn(src[k]);
            int seg = ch >> 3, pc = (ch & 7) ^ (vr & 7);
            size_t ge = ((size_t)b * DD + vr) * LL + l0 + seg * 64 + pc * 8;
            *(uint4*)&g_vhi[ge] = *(uint4*)hi8;
        }
    } else if (o0 < 512) {
        // K: transposed [l][512] pre-swizzled, hi only
        #pragma unroll
        for (int i = tid; i < 2048; i += 256) {
            int l = i >> 4, ch = i & 15;
            int gl = l0 + l;
            __align__(16) __half hi8[8];
            #pragma unroll
            for (int k = 0; k < 8; k++) {
                int rk = (k + lane) & 7;
                hi8[rk] = __float2half_rn(Osm[(ch * 8 + rk) * OSTRIDE + l]);
            }
            int seg = ch >> 3, pc = (ch & 7) ^ (gl & 7);
            size_t ge = ((size_t)b * LL + gl) * DD + o0 + seg * 64 + pc * 8;
            *(uint4*)&g_khi[ge] = *(uint4*)hi8;
        }
    } else {
        // Q: transposed [l][512] pre-swizzled, hi only, scaled
        #pragma unroll
        for (int i = tid; i < 2048; i += 256) {
            int l = i >> 4, ch = i & 15;
            int gl = l0 + l;
            __align__(16) __half hi8[8];
            #pragma unroll
            for (int k = 0; k < 8; k++) {
                int rk = (k + lane) & 7;
                hi8[rk] = __float2half_rn(Osm[(ch * 8 + rk) * OSTRIDE + l] * 0.125f);
            }
            int seg = ch >> 3, pc = (ch & 7) ^ (gl & 7);
            size_t ge = ((size_t)b * LL + gl) * DD + (o0 - 1024) + seg * 64 + pc * 8;
            *(uint4*)&g_qhi[ge] = *(uint4*)hi8;
        }
    }
}

// ===========================================================================
// mma.sync flash attention (pure fp16): Q frags in registers, triple-buffered
// cp.async staging (2-deep prefetch), one __syncthreads per iteration.
// ===========================================================================
#define ST_SIZE  16640            // KHI 8K | VHI 8K | MSK 256
#define SM_TOTAL (3 * ST_SIZE)    // 49920

__global__ __launch_bounds__(256, 2) void attn_mma(
    const int* __restrict__ mask, float* __restrict__ out)
{
    extern __shared__ char smem[];
    const uint32_t sb = smem_u32(smem);
    const int tid  = threadIdx.x;
    const int w    = tid >> 5;
    const int lane = tid & 31;
    const int b = blockIdx.z, h = blockIdx.y, q0 = blockIdx.x * 128;

    const size_t qkrow0 = (size_t)b * LL * DD + (size_t)h * 64;   // + l*DD
    const size_t vrow0  = ((size_t)b * DD + h * 64) * LL;         // + dh*LL

    // staging geometry: thread copies rows {srow, srow+32}, chunk sch
    const int srow = tid >> 3;         // 0..31
    const int sch  = tid & 7;
    const uint32_t sd = (uint32_t)(srow * 128 + sch * 16);

    // incremental gmem pointers (advance per tile)
    const __half* pkh = g_khi + qkrow0 + (size_t)srow * DD + sch * 8;
    const __half* pvh = g_vhi + vrow0 + (size_t)srow * LL + sch * 8;
    const int*    pmk = mask + (size_t)b * LL + tid * 4;

#define PREFETCH_TILE(stb) do { \
    cpa16((stb) + sd,                pkh); \
    cpa16((stb) + sd + 4096,         pkh + 32 * DD); \
    cpa16((stb) + 8192 + sd,         pvh); \
    cpa16((stb) + 8192 + sd + 4096,  pvh + (size_t)32 * LL); \
    if (tid < 16) cpa16((stb) + 16384 + tid * 16, pmk); \
    pkh += 64 * DD; pvh += 64; pmk += 64; \
} while (0)

    // ---- group 1: Q (128 rows) into buf2 region ----
    {
        const __half* pq = g_qhi + qkrow0 + (size_t)(q0 + srow) * DD + sch * 8;
        const uint32_t qst = sb + 2 * ST_SIZE;
        cpa16(qst + sd,          pq);
        cpa16(qst + sd + 4096,   pq + 32 * DD);
        cpa16(qst + sd + 8192,   pq + 64 * DD);
        cpa16(qst + sd + 12288,  pq + 96 * DD);
        CPA_COMMIT();
    }
    // ---- groups 2,3: tiles 0,1 ----
    PREFETCH_TILE(sb);             CPA_COMMIT();
    PREFETCH_TILE(sb + ST_SIZE);   CPA_COMMIT();

    const int mi = lane >> 3;
    const int qrow_l = w * 16 + ((mi & 1) << 3) + (lane & 7);
    const int a_colh = (mi >> 1) * 16;
    const int b_rsub = ((mi >> 1) << 3) + (lane & 7);
    const int b_colh = (mi & 1) * 16;

    // ---- extract Q fragments into registers ----
    CPA_WAIT(2);
    __syncthreads();
    uint32_t qf[4][4];
    {
        const uint32_t qb2 = sb + 2 * ST_SIZE;
        #pragma unroll
        for (int kc = 0; kc < 4; kc++) {
            uint32_t qoff = (uint32_t)(qrow_l * 128 + kc * 32 + a_colh);
            ldsm4(qf[kc], qb2 + SWZ128(qoff));
        }
    }
    __syncthreads();   // Q frags extracted before iter0 prefetch clobbers buf2

    float o_acc[8][4];
    #pragma unroll
    for (int i = 0; i < 8; i++)
        #pragma unroll
        for (int j = 0; j < 4; j++) o_acc[i][j] = 0.f;
    float lsum0 = 0.f, lsum1 = 0.f;

    uint32_t stc = sb;                 // buffer holding current tile
    uint32_t stn = sb + 2 * ST_SIZE;   // buffer for tile it+2

    for (int it = 0; it < 32; it++) {
        if (it == 31) { CPA_WAIT(0); } else { CPA_WAIT(1); }
        __syncthreads();

        if (it + 2 < 32) {
            PREFETCH_TILE(stn);
            CPA_COMMIT();
            stn = (stn == sb + 2 * ST_SIZE) ? sb : stn + ST_SIZE;
        }

        const uint32_t kh = stc, vh = stc + 8192;
        const int* mp = (const int*)(smem + (stc - sb) + 16384);

        // ---- S = Q_hi.K_hi^T ----
        float s[8][4];
        #pragma unroll
        for (int i = 0; i < 8; i++)
            #pragma unroll
            for (int j = 0; j < 4; j++) s[i][j] = 0.f;

        #pragma unroll
        for (int kc = 0; kc < 4; kc++) {
            #pragma unroll
            for (int j = 0; j < 8; j += 2) {
                uint32_t bhi[4];
                uint32_t koff = (uint32_t)((j * 8 + b_rsub) * 128 + kc * 32 + b_colh);
                ldsm4(bhi, kh + SWZ128(koff));
                mma16816(s[j],     qf[kc], bhi);
                mma16816(s[j + 1], qf[kc], bhi + 2);
            }
        }

        // ---- softmax + P_hi packing ----
        uint32_t phiA[8], phiB[8];
        #pragma unroll
        for (int nt = 0; nt < 8; nt++) {
            const int c0 = nt * 8 + ((lane & 3) << 1);
            const bool m0v = mp[c0] != 0, m1v = mp[c0 + 1] != 0;
            float p0 = m0v ? __expf(s[nt][0]) : 0.f;
            float p1 = m1v ? __expf(s[nt][1]) : 0.f;
            float p2 = m0v ? __expf(s[nt][2]) : 0.f;
            float p3 = m1v ? __expf(s[nt][3]) : 0.f;
            lsum0 += p0 + p1;
            lsum1 += p2 + p3;
            __half2 hA, hB;
            hA.x = __float2half_rn(p0); hA.y = __float2half_rn(p1);
            hB.x = __float2half_rn(p2); hB.y = __float2half_rn(p3);
            phiA[nt] = *(uint32_t*)&hA; phiB[nt] = *(uint32_t*)&hB;
        }

        // ---- O += P_hi.V_hi ----
        #pragma unroll
        for (int kc = 0; kc < 4; kc++) {
            uint32_t ahi[4] = {phiA[2 * kc], phiB[2 * kc], phiA[2 * kc + 1], phiB[2 * kc + 1]};
            #pragma unroll
            for (int j = 0; j < 8; j += 2) {
                uint32_t bhi[4];
                uint32_t voff = (uint32_t)((j * 8 + b_rsub) * 128 + kc * 32 + b_colh);
                ldsm4(bhi, vh + SWZ128(voff));
                mma16816(o_acc[j],     ahi, bhi);
                mma16816(o_acc[j + 1], ahi, bhi + 2);
            }
        }

        stc = (stc == sb + 2 * ST_SIZE) ? sb : stc + ST_SIZE;
    }

    __syncthreads();   // all tile reads done before smem reuse as Osm

    #pragma unroll
    for (int off = 1; off < 4; off <<= 1) {
        lsum0 += __shfl_xor_sync(0xffffffffu, lsum0, off);
        lsum1 += __shfl_xor_sync(0xffffffffu, lsum1, off);
    }
    const float inv0 = 1.0f / lsum0, inv1 = 1.0f / lsum1;

    float* Osm = (float*)smem;
    const int r1 = w * 16 + (lane >> 2);
    const int cb = (lane & 3) << 1;
    #pragma unroll
    for (int nt = 0; nt < 8; nt++) {
        const int c0 = nt * 8 + cb;
        Osm[r1 * 66 + c0]           = o_acc[nt][0] * inv0;
        Osm[r1 * 66 + c0 + 1]       = o_acc[nt][1] * inv0;
        Osm[(r1 + 8) * 66 + c0]     = o_acc[nt][2] * inv1;
        Osm[(r1 + 8) * 66 + c0 + 1] = o_acc[nt][3] * inv1;
    }
    __syncthreads();
    {
        const int dh = tid >> 2;
        const int qc = (tid & 3) << 5;
        float* op = out + ((size_t)b * DD + h * 64 + dh) * LL + q0 + qc;
        #pragma unroll
        for (int i = 0; i < 8; i++) {
            float4 v = make_float4(Osm[(qc + 4 * i + 0) * 66 + dh],
                                   Osm[(qc + 4 * i + 1) * 66 + dh],
                                   Osm[(qc + 4 * i + 2) * 66 + dh],
                                   Osm[(qc + 4 * i + 3) * 66 + dh]);
            *(float4*)(op + 4 * i) = v;
        }
    }
}

// ===========================================================================
extern "C" void kernel_launch(void* const* d_in, const int* in_sizes, int n_in,
                              void* d_out, int out_size) {
    (void)in_sizes; (void)n_in; (void)out_size;
    const float* queries = (const float*)d_in[0];
    const int*   mask    = (const int*)d_in[1];
    const float* w_mem   = (const float*)d_in[2];
    const float* w_q     = (const float*)d_in[3];
    float* out = (float*)d_out;

    cudaFuncSetAttribute(proj_mma, cudaFuncAttributeMaxDynamicSharedMemorySize, P_TOTAL);
    dim3 gp(LL / 128, OT / 128, BB);
    proj_mma<<<gp, 256, P_TOTAL>>>(queries, w_mem, w_q);

    cudaFuncSetAttribute(attn_mma, cudaFuncAttributeMaxDynamicSharedMemorySize, SM_TOTAL);
    dim3 ga(LL / 128, HH, BB);
    attn_mma<<<ga, 256, SM_TOTAL>>>(mask, out);
}

// round 12
// speedup vs baseline: 1.9287x; 1.1998x over previous
#include <cuda_runtime.h>
#include <cuda_fp16.h>
#include <cstdint>
#include <math.h>

#define BB 8
#define DD 512
#define LL 2048
#define HH 8

// fp16 scratch, all pre-swizzled (SW128 chunk perm by row&7 within 64-elem segs)
__device__ __half g_qhi[(size_t)BB * LL * DD];            // [b][l][512] (attn Q)
__device__ __half g_khi[(size_t)BB * LL * DD];            // [b][l][512] (attn K)
__device__ __half g_vhi[(size_t)BB * DD * LL];            // [b][dh][l]  (attn V)
__device__ __half g_whi[(size_t)1536 * DD];               // [o][512]    (proj A, hi)
__device__ __half g_xhi[(size_t)BB * DD * LL];            // [b][d][l]   (proj B hi)
__device__ __half g_xlo[(size_t)BB * DD * LL];            // [b][d][l]   (proj B lo)

// ============================ helpers ======================================
__device__ __forceinline__ uint32_t smem_u32(const void* p) {
    uint32_t a;
    asm("{ .reg .u64 t; cvta.to.shared.u64 t, %1; cvt.u32.u64 %0, t; }"
        : "=r"(a) : "l"(p));
    return a;
}

#define SWZ128(off) ((off) ^ (((off) >> 3) & 0x70))

__device__ __forceinline__ void ldsm4(uint32_t* r, uint32_t addr) {
    asm volatile("ldmatrix.sync.aligned.m8n8.x4.shared.b16 {%0,%1,%2,%3}, [%4];"
        : "=r"(r[0]), "=r"(r[1]), "=r"(r[2]), "=r"(r[3]) : "r"(addr));
}

__device__ __forceinline__ void ldsm4t(uint32_t* r, uint32_t addr) {
    asm volatile("ldmatrix.sync.aligned.m8n8.x4.trans.shared.b16 {%0,%1,%2,%3}, [%4];"
        : "=r"(r[0]), "=r"(r[1]), "=r"(r[2]), "=r"(r[3]) : "r"(addr));
}

__device__ __forceinline__ void mma16816(float* d, const uint32_t* a, const uint32_t* b) {
    asm volatile("mma.sync.aligned.m16n8k16.row.col.f32.f16.f16.f32 "
        "{%0,%1,%2,%3}, {%4,%5,%6,%7}, {%8,%9}, {%0,%1,%2,%3};"
        : "+f"(d[0]), "+f"(d[1]), "+f"(d[2]), "+f"(d[3])
        : "r"(a[0]), "r"(a[1]), "r"(a[2]), "r"(a[3]), "r"(b[0]), "r"(b[1]));
}

__device__ __forceinline__ void cpa16(uint32_t sdst, const void* gsrc) {
    asm volatile("cp.async.cg.shared.global [%0], [%1], 16;"
        :: "r"(sdst), "l"(gsrc));
}
#define CPA_COMMIT() asm volatile("cp.async.commit_group;" ::: "memory")
#define CPA_WAIT(n)  asm volatile("cp.async.wait_group %0;" :: "n"(n) : "memory")

// ===========================================================================
// One-shot conversion kernels (fp32 -> pre-swizzled fp16 gmem)
// ===========================================================================
__global__ void cvt_w(const float* __restrict__ w_mem, const float* __restrict__ w_q) {
    int idx = blockIdx.x * 256 + threadIdx.x;     // 1536*64 = 98304
    int o = idx >> 6, ch = idx & 63;
    int seg = ch >> 3, c8 = ch & 7;
    const float* src = (o < 1024 ? w_mem + (size_t)o * DD
                                 : w_q + (size_t)(o - 1024) * DD) + seg * 64 + c8 * 8;
    float4 v0 = *(const float4*)src, v1 = *(const float4*)(src + 4);
    __align__(16) __half h8[8];
    h8[0] = __float2half_rn(v0.x); h8[1] = __float2half_rn(v0.y);
    h8[2] = __float2half_rn(v0.z); h8[3] = __float2half_rn(v0.w);
    h8[4] = __float2half_rn(v1.x); h8[5] = __float2half_rn(v1.y);
    h8[6] = __float2half_rn(v1.z); h8[7] = __float2half_rn(v1.w);
    int pc = c8 ^ (o & 7);
    *(uint4*)&g_whi[(size_t)o * DD + seg * 64 + pc * 8] = *(uint4*)h8;
}

__global__ void cvt_q(const float* __restrict__ qin) {
    int idx = blockIdx.x * 256 + threadIdx.x;     // 8*512*256 = 1048576
    int b = idx >> 17;
    int r = idx & 131071;
    int d = r >> 8, ch = r & 255;
    int seg = ch >> 3, c8 = ch & 7;
    size_t base = ((size_t)b * DD + d) * LL;
    const float* src = qin + base + seg * 64 + c8 * 8;
    float4 v0 = *(const float4*)src, v1 = *(const float4*)(src + 4);
    __align__(16) __half hi8[8], lo8[8];
    float vv[8] = {v0.x, v0.y, v0.z, v0.w, v1.x, v1.y, v1.z, v1.w};
    #pragma unroll
    for (int k = 0; k < 8; k++) {
        __half hx = __float2half_rn(vv[k]);
        hi8[k] = hx;
        lo8[k] = __float2half_rn(vv[k] - __half2float(hx));
    }
    int pc = c8 ^ (d & 7);
    size_t ge = base + seg * 64 + pc * 8;
    *(uint4*)&g_xhi[ge] = *(uint4*)hi8;
    *(uint4*)&g_xlo[ge] = *(uint4*)lo8;
}

// ===========================================================================
// Projection GEMM (tensor pipe, fp16 2-term, cp.async double-buffered):
//   out2[o][l] = sum_d W_hi[o][d] * (x_hi + x_lo)[d][l]
// Epilogue: q/k -> [l][512] hi, v -> [dh][l] hi, all pre-swizzled.
// ===========================================================================
#define PJ_A    0
#define PJ_B0H  16384
#define PJ_B0L  24576
#define PJ_B1H  32768
#define PJ_B1L  40960
#define PJBUF   49152
#define OSTRIDE 132
#define P_TOTAL (2 * PJBUF)      // 98304 (>= 67584 epilogue)

__global__ __launch_bounds__(256, 2) void proj_mma() {
    extern __shared__ char smem[];
    const uint32_t sb = smem_u32(smem);
    const int tid = threadIdx.x;
    const int w = tid >> 5, lane = tid & 31;
    const int b  = blockIdx.z;
    const int l0 = blockIdx.x * 128;
    const int o0 = blockIdx.y * 128;

    // staging: thread copies chunk sch of rows {srow, srow+32, ...}
    const int srow = tid >> 3, sch = tid & 7;
    const uint32_t sda = (uint32_t)(srow * 128 + sch * 16);
    const __half* pw  = g_whi + (size_t)(o0 + srow) * DD + sch * 8;
    const __half* pxh = g_xhi + ((size_t)b * DD + srow) * LL + l0 + sch * 8;
    const __half* pxl = g_xlo + ((size_t)b * DD + srow) * LL + l0 + sch * 8;

#define PREFETCH_PJ(stb) do { \
    cpa16((stb) + PJ_A + sda,          pw); \
    cpa16((stb) + PJ_A + sda + 4096,   pw + 32 * DD); \
    cpa16((stb) + PJ_A + sda + 8192,   pw + 64 * DD); \
    cpa16((stb) + PJ_A + sda + 12288,  pw + 96 * DD); \
    cpa16((stb) + PJ_B0H + sda,        pxh); \
    cpa16((stb) + PJ_B0H + sda + 4096, pxh + (size_t)32 * LL); \
    cpa16((stb) + PJ_B1H + sda,        pxh + 64); \
    cpa16((stb) + PJ_B1H + sda + 4096, pxh + (size_t)32 * LL + 64); \
    cpa16((stb) + PJ_B0L + sda,        pxl); \
    cpa16((stb) + PJ_B0L + sda + 4096, pxl + (size_t)32 * LL); \
    cpa16((stb) + PJ_B1L + sda,        pxl + 64); \
    cpa16((stb) + PJ_B1L + sda + 4096, pxl + (size_t)32 * LL + 64); \
    pw += 64; pxh += (size_t)64 * LL; pxl += (size_t)64 * LL; \
} while (0)

    PREFETCH_PJ(sb);
    CPA_COMMIT();

    const int mi     = lane >> 3;
    const int arow   = w * 16 + ((mi & 1) << 3) + (lane & 7);
    const int acolh  = (mi >> 1) * 16;
    const int b_ksub = ((mi & 1) << 3) + (lane & 7);
    const int b_noct = mi >> 1;

    float c[16][4];
    #pragma unroll
    for (int i = 0; i < 16; i++)
        #pragma unroll
        for (int j = 0; j < 4; j++) c[i][j] = 0.f;

    uint32_t bufc = sb, bufn = sb + PJBUF;
    for (int kc = 0; kc < 8; kc++) {
        CPA_WAIT(0);
        __syncthreads();
        if (kc + 1 < 8) {
            PREFETCH_PJ(bufn);
            CPA_COMMIT();
        }

        #pragma unroll
        for (int ks = 0; ks < 4; ks++) {
            uint32_t ahi[4];
            uint32_t aoff = (uint32_t)(arow * 128 + ks * 32 + acolh);
            ldsm4(ahi, bufc + PJ_A + SWZ128(aoff));
            #pragma unroll
            for (int hb = 0; hb < 2; hb++) {
                const uint32_t bh = bufc + (hb ? PJ_B1H : PJ_B0H);
                const uint32_t bl = bufc + (hb ? PJ_B1L : PJ_B0L);
                #pragma unroll
                for (int j = 0; j < 8; j += 2) {
                    uint32_t boff = (uint32_t)((ks * 16 + b_ksub) * 128 + (j + b_noct) * 16);
                    uint32_t bhi[4], blo[4];
                    ldsm4t(bhi, bh + SWZ128(boff));
                    ldsm4t(blo, bl + SWZ128(boff));
                    const int o1 = hb * 8 + j;
                    mma16816(c[o1],     ahi, bhi);
                    mma16816(c[o1],     ahi, blo);
                    mma16816(c[o1 + 1], ahi, bhi + 2);
                    mma16816(c[o1 + 1], ahi, blo + 2);
                }
            }
        }

        uint32_t t = bufc; bufc = bufn; bufn = t;
    }

    // ---- fragments -> smem [o][OSTRIDE] fp32 ----
    __syncthreads();
    float* Osm = (float*)smem;
    {
        const int r1 = w * 16 + (lane >> 2);
        const int cb = (lane & 3) << 1;
        #pragma unroll
        for (int oct = 0; oct < 16; oct++) {
            const int col = (oct >> 3) * 64 + (oct & 7) * 8 + cb;
            Osm[r1 * OSTRIDE + col]           = c[oct][0];
            Osm[r1 * OSTRIDE + col + 1]       = c[oct][1];
            Osm[(r1 + 8) * OSTRIDE + col]     = c[oct][2];
            Osm[(r1 + 8) * OSTRIDE + col + 1] = c[oct][3];
        }
    }
    __syncthreads();

    if (o0 >= 512 && o0 < 1024) {
        // V: [dh][l] pre-swizzled, hi only
        #pragma unroll
        for (int i = tid; i < 2048; i += 256) {
            int row = i >> 4, ch = i & 15;
            int vr = (o0 - 512) + row;
            const float* src = &Osm[row * OSTRIDE + ch * 8];
            __align__(16) __half hi8[8];
            #pragma unroll
            for (int k = 0; k < 8; k++)
                hi8[k] = __float2half_rn(src[k]);
            int seg = ch >> 3, pc = (ch & 7) ^ (vr & 7);
            size_t ge = ((size_t)b * DD + vr) * LL + l0 + seg * 64 + pc * 8;
            *(uint4*)&g_vhi[ge] = *(uint4*)hi8;
        }
    } else if (o0 < 512) {
        // K: transposed [l][512] pre-swizzled, hi only
        #pragma unroll
        for (int i = tid; i < 2048; i += 256) {
            int l = i >> 4, ch = i & 15;
            int gl = l0 + l;
            __align__(16) __half hi8[8];
            #pragma unroll
            for (int k = 0; k < 8; k++) {
                int rk = (k + lane) & 7;
                hi8[rk] = __float2half_rn(Osm[(ch * 8 + rk) * OSTRIDE + l]);
            }
            int seg = ch >> 3, pc = (ch & 7) ^ (gl & 7);
            size_t ge = ((size_t)b * LL + gl) * DD + o0 + seg * 64 + pc * 8;
            *(uint4*)&g_khi[ge] = *(uint4*)hi8;
        }
    } else {
        // Q: transposed [l][512] pre-swizzled, hi only, scaled
        #pragma unroll
        for (int i = tid; i < 2048; i += 256) {
            int l = i >> 4, ch = i & 15;
            int gl = l0 + l;
            __align__(16) __half hi8[8];
            #pragma unroll
            for (int k = 0; k < 8; k++) {
                int rk = (k + lane) & 7;
                hi8[rk] = __float2half_rn(Osm[(ch * 8 + rk) * OSTRIDE + l] * 0.125f);
            }
            int seg = ch >> 3, pc = (ch & 7) ^ (gl & 7);
            size_t ge = ((size_t)b * LL + gl) * DD + (o0 - 1024) + seg * 64 + pc * 8;
            *(uint4*)&g_qhi[ge] = *(uint4*)hi8;
        }
    }
}

// ===========================================================================
// mma.sync flash attention (pure fp16, unchanged from Round 11, validated)
// ===========================================================================
#define ST_SIZE  16640            // KHI 8K | VHI 8K | MSK 256
#define SM_TOTAL (3 * ST_SIZE)    // 49920

__global__ __launch_bounds__(256, 2) void attn_mma(
    const int* __restrict__ mask, float* __restrict__ out)
{
    extern __shared__ char smem[];
    const uint32_t sb = smem_u32(smem);
    const int tid  = threadIdx.x;
    const int w    = tid >> 5;
    const int lane = tid & 31;
    const int b = blockIdx.z, h = blockIdx.y, q0 = blockIdx.x * 128;

    const size_t qkrow0 = (size_t)b * LL * DD + (size_t)h * 64;
    const size_t vrow0  = ((size_t)b * DD + h * 64) * LL;

    const int srow = tid >> 3;
    const int sch  = tid & 7;
    const uint32_t sd = (uint32_t)(srow * 128 + sch * 16);

    const __half* pkh = g_khi + qkrow0 + (size_t)srow * DD + sch * 8;
    const __half* pvh = g_vhi + vrow0 + (size_t)srow * LL + sch * 8;
    const int*    pmk = mask + (size_t)b * LL + tid * 4;

#define PREFETCH_TILE(stb) do { \
    cpa16((stb) + sd,                pkh); \
    cpa16((stb) + sd + 4096,         pkh + 32 * DD); \
    cpa16((stb) + 8192 + sd,         pvh); \
    cpa16((stb) + 8192 + sd + 4096,  pvh + (size_t)32 * LL); \
    if (tid < 16) cpa16((stb) + 16384 + tid * 16, pmk); \
    pkh += 64 * DD; pvh += 64; pmk += 64; \
} while (0)

    {
        const __half* pq = g_qhi + qkrow0 + (size_t)(q0 + srow) * DD + sch * 8;
        const uint32_t qst = sb + 2 * ST_SIZE;
        cpa16(qst + sd,          pq);
        cpa16(qst + sd + 4096,   pq + 32 * DD);
        cpa16(qst + sd + 8192,   pq + 64 * DD);
        cpa16(qst + sd + 12288,  pq + 96 * DD);
        CPA_COMMIT();
    }
    PREFETCH_TILE(sb);             CPA_COMMIT();
    PREFETCH_TILE(sb + ST_SIZE);   CPA_COMMIT();

    const int mi = lane >> 3;
    const int qrow_l = w * 16 + ((mi & 1) << 3) + (lane & 7);
    const int a_colh = (mi >> 1) * 16;
    const int b_rsub = ((mi >> 1) << 3) + (lane & 7);
    const int b_colh = (mi & 1) * 16;

    CPA_WAIT(2);
    __syncthreads();
    uint32_t qf[4][4];
    {
        const uint32_t qb2 = sb + 2 * ST_SIZE;
        #pragma unroll
        for (int kc = 0; kc < 4; kc++) {
            uint32_t qoff = (uint32_t)(qrow_l * 128 + kc * 32 + a_colh);
            ldsm4(qf[kc], qb2 + SWZ128(qoff));
        }
    }
    __syncthreads();

    float o_acc[8][4];
    #pragma unroll
    for (int i = 0; i < 8; i++)
        #pragma unroll
        for (int j = 0; j < 4; j++) o_acc[i][j] = 0.f;
    float lsum0 = 0.f, lsum1 = 0.f;

    uint32_t stc = sb;
    uint32_t stn = sb + 2 * ST_SIZE;

    for (int it = 0; it < 32; it++) {
        if (it == 31) { CPA_WAIT(0); } else { CPA_WAIT(1); }
        __syncthreads();

        if (it + 2 < 32) {
            PREFETCH_TILE(stn);
            CPA_COMMIT();
            stn = (stn == sb + 2 * ST_SIZE) ? sb : stn + ST_SIZE;
        }

        const uint32_t kh = stc, vh = stc + 8192;
        const int* mp = (const int*)(smem + (stc - sb) + 16384);

        float s[8][4];
        #pragma unroll
        for (int i = 0; i < 8; i++)
            #pragma unroll
            for (int j = 0; j < 4; j++) s[i][j] = 0.f;

        #pragma unroll
        for (int kc = 0; kc < 4; kc++) {
            #pragma unroll
            for (int j = 0; j < 8; j += 2) {
                uint32_t bhi[4];
                uint32_t koff = (uint32_t)((j * 8 + b_rsub) * 128 + kc * 32 + b_colh);
                ldsm4(bhi, kh + SWZ128(koff));
                mma16816(s[j],     qf[kc], bhi);
                mma16816(s[j + 1], qf[kc], bhi + 2);
            }
        }

        uint32_t phiA[8], phiB[8];
        #pragma unroll
        for (int nt = 0; nt < 8; nt++) {
            const int c0 = nt * 8 + ((lane & 3) << 1);
            const bool m0v = mp[c0] != 0, m1v = mp[c0 + 1] != 0;
            float p0 = m0v ? __expf(s[nt][0]) : 0.f;
            float p1 = m1v ? __expf(s[nt][1]) : 0.f;
            float p2 = m0v ? __expf(s[nt][2]) : 0.f;
            float p3 = m1v ? __expf(s[nt][3]) : 0.f;
            lsum0 += p0 + p1;
            lsum1 += p2 + p3;
            __half2 hA, hB;
            hA.x = __float2half_rn(p0); hA.y = __float2half_rn(p1);
            hB.x = __float2half_rn(p2); hB.y = __float2half_rn(p3);
            phiA[nt] = *(uint32_t*)&hA; phiB[nt] = *(uint32_t*)&hB;
        }

        #pragma unroll
        for (int kc = 0; kc < 4; kc++) {
            uint32_t ahi[4] = {phiA[2 * kc], phiB[2 * kc], phiA[2 * kc + 1], phiB[2 * kc + 1]};
            #pragma unroll
            for (int j = 0; j < 8; j += 2) {
                uint32_t bhi[4];
                uint32_t voff = (uint32_t)((j * 8 + b_rsub) * 128 + kc * 32 + b_colh);
                ldsm4(bhi, vh + SWZ128(voff));
                mma16816(o_acc[j],     ahi, bhi);
                mma16816(o_acc[j + 1], ahi, bhi + 2);
            }
        }

        stc = (stc == sb + 2 * ST_SIZE) ? sb : stc + ST_SIZE;
    }

    __syncthreads();

    #pragma unroll
    for (int off = 1; off < 4; off <<= 1) {
        lsum0 += __shfl_xor_sync(0xffffffffu, lsum0, off);
        lsum1 += __shfl_xor_sync(0xffffffffu, lsum1, off);
    }
    const float inv0 = 1.0f / lsum0, inv1 = 1.0f / lsum1;

    float* Osm = (float*)smem;
    const int r1 = w * 16 + (lane >> 2);
    const int cb = (lane & 3) << 1;
    #pragma unroll
    for (int nt = 0; nt < 8; nt++) {
        const int c0 = nt * 8 + cb;
        Osm[r1 * 66 + c0]           = o_acc[nt][0] * inv0;
        Osm[r1 * 66 + c0 + 1]       = o_acc[nt][1] * inv0;
        Osm[(r1 + 8) * 66 + c0]     = o_acc[nt][2] * inv1;
        Osm[(r1 + 8) * 66 + c0 + 1] = o_acc[nt][3] * inv1;
    }
    __syncthreads();
    {
        const int dh = tid >> 2;
        const int qc = (tid & 3) << 5;
        float* op = out + ((size_t)b * DD + h * 64 + dh) * LL + q0 + qc;
        #pragma unroll
        for (int i = 0; i < 8; i++) {
            float4 v = make_float4(Osm[(qc + 4 * i + 0) * 66 + dh],
                                   Osm[(qc + 4 * i + 1) * 66 + dh],
                                   Osm[(qc + 4 * i + 2) * 66 + dh],
                                   Osm[(qc + 4 * i + 3) * 66 + dh]);
            *(float4*)(op + 4 * i) = v;
        }
    }
}

// ===========================================================================
extern "C" void kernel_launch(void* const* d_in, const int* in_sizes, int n_in,
                              void* d_out, int out_size) {
    (void)in_sizes; (void)n_in; (void)out_size;
    const float* queries = (const float*)d_in[0];
    const int*   mask    = (const int*)d_in[1];
    const float* w_mem   = (const float*)d_in[2];
    const float* w_q     = (const float*)d_in[3];
    float* out = (float*)d_out;

    cvt_w<<<384, 256>>>(w_mem, w_q);
    cvt_q<<<4096, 256>>>(queries);

    cudaFuncSetAttribute(proj_mma, cudaFuncAttributeMaxDynamicSharedMemorySize, P_TOTAL);
    dim3 gp(LL / 128, 1536 / 128, BB);
    proj_mma<<<gp, 256, P_TOTAL>>>();

    cudaFuncSetAttribute(attn_mma, cudaFuncAttributeMaxDynamicSharedMemorySize, SM_TOTAL);
    dim3 ga(LL / 128, HH, BB);
    attn_mma<<<ga, 256, SM_TOTAL>>>(mask, out);
}